// round 10
// baseline (speedup 1.0000x reference)
#include <cuda_runtime.h>
#include <cuda_bf16.h>
#include <math.h>
#include <stdint.h>

#define Bv   4
#define Cv   64
#define Hv   160
#define Wv   160
#define HWv  25600
#define KKv  9
#define OMC  27
#define CKK  576

#define MT    128          // px per block tile (M)
#define TPB   256
#define CKC   64           // K chunk = one kernel tap (64 channels)
#define NCH   9

// swizzled tile: row = 128B = 8 uint4; quad col stored at (cq ^ (row&7))

// dcn smem offsets (bytes)
#define DS_SC   0          // float[64]
#define DS_SH   256        // float[64]
#define DS_AH   512        // 128*128 = 16384
#define DS_AL   16896      // 16384
#define DS_BH   33280      // 64*128 = 8192
#define DS_BL   41472      // 8192
#define DS_TOT  49664

// offc smem offsets
#define OS_AH   0          // 16384
#define OS_AL   16384      // 16384
#define OS_BH   32768      // 32*128 = 4096
#define OS_BL   36864      // 4096
#define OS_BIAS 40960      // 128
#define OS_TOT  41088

// scratch
__device__ float    g_om[Bv*OMC*HWv];
__device__ float    g_mid[Bv*Cv*HWv];
__device__ uint32_t g_xhl[Bv*Cv*HWv];     // packed (bf16 hi | bf16 lo<<16)
__device__ uint32_t g_midhl[Bv*Cv*HWv];
// k-major weights: [o][k*64 + c]
__device__ __align__(16) __nv_bfloat16 g_wh1[Cv*CKK], g_wl1[Cv*CKK];
__device__ __align__(16) __nv_bfloat16 g_wh2[Cv*CKK], g_wl2[Cv*CKK];
__device__ __align__(16) __nv_bfloat16 g_omh1[32*CKK], g_oml1[32*CKK];
__device__ __align__(16) __nv_bfloat16 g_omh2[32*CKK], g_oml2[32*CKK];

__device__ __forceinline__ float gelu_exact(float v) {
    return 0.5f * v * (1.0f + erff(v * 0.70710678118654752f));
}
__device__ __forceinline__ uint32_t split_pack(float v) {
    __nv_bfloat16 h = __float2bfloat16(v);
    __nv_bfloat16 l = __float2bfloat16(v - __bfloat162float(h));
    return (uint32_t)__bfloat16_as_ushort(h) | ((uint32_t)__bfloat16_as_ushort(l) << 16);
}
__device__ __forceinline__ uint32_t smem_u32(const void* p) {
    uint32_t a;
    asm("{ .reg .u64 t; cvta.to.shared.u64 t, %1; cvt.u32.u64 %0, t; }" : "=r"(a) : "l"(p));
    return a;
}
__device__ __forceinline__ void mma_bf16(float* d,
    uint32_t a0, uint32_t a1, uint32_t a2, uint32_t a3, uint32_t b0, uint32_t b1)
{
    asm volatile(
        "mma.sync.aligned.m16n8k16.row.col.f32.bf16.bf16.f32 "
        "{%0,%1,%2,%3},{%4,%5,%6,%7},{%8,%9},{%0,%1,%2,%3};"
        : "+f"(d[0]), "+f"(d[1]), "+f"(d[2]), "+f"(d[3])
        : "r"(a0), "r"(a1), "r"(a2), "r"(a3), "r"(b0), "r"(b1));
}
__device__ __forceinline__ void ldm_x4(uint32_t& r0, uint32_t& r1, uint32_t& r2, uint32_t& r3, uint32_t addr) {
    asm volatile("ldmatrix.sync.aligned.m8n8.x4.shared.b16 {%0,%1,%2,%3}, [%4];"
                 : "=r"(r0), "=r"(r1), "=r"(r2), "=r"(r3) : "r"(addr));
}
// swizzled byte offset within a tile: row (128B rows), quad column cq
__device__ __forceinline__ uint32_t swz(int row, int cq) {
    return (uint32_t)(row*128 + ((cq ^ (row & 7)) << 4));
}

// ---------------------------------------------------------------------------
// prep: split to bf16 hi/lo; weights permuted to k-major [o][k*64+c]
// ---------------------------------------------------------------------------
__global__ void prep_kernel(const float* __restrict__ x,
                            const float* __restrict__ wd1, const float* __restrict__ wd2,
                            const float* __restrict__ wom1, const float* __restrict__ wom2)
{
    int i = blockIdx.x * 256 + threadIdx.x;
    if (i < Bv*Cv*HWv) g_xhl[i] = split_pack(x[i]);
    if (i < Cv*CKK) {
        int o = i / CKK, r = i - o*CKK;
        int c = r / 9, k = r - 9*c;
        int dst = o*CKK + k*64 + c;
        float v1 = wd1[i];
        __nv_bfloat16 h1 = __float2bfloat16(v1);
        g_wh1[dst] = h1;
        g_wl1[dst] = __float2bfloat16(v1 - __bfloat162float(h1));
        float v2 = wd2[i];
        __nv_bfloat16 h2 = __float2bfloat16(v2);
        g_wh2[dst] = h2;
        g_wl2[dst] = __float2bfloat16(v2 - __bfloat162float(h2));
    }
    if (i < 32*CKK) {
        int o = i / CKK, r = i - o*CKK;
        int c = r / 9, k = r - 9*c;
        int dst = o*CKK + k*64 + c;
        float v1 = (i < OMC*CKK) ? wom1[i] : 0.f;
        __nv_bfloat16 h1 = __float2bfloat16(v1);
        g_omh1[dst] = h1;
        g_oml1[dst] = __float2bfloat16(v1 - __bfloat162float(h1));
        float v2 = (i < OMC*CKK) ? wom2[i] : 0.f;
        __nv_bfloat16 h2 = __float2bfloat16(v2);
        g_omh2[dst] = h2;
        g_oml2[dst] = __float2bfloat16(v2 - __bfloat162float(h2));
    }
}

// ---------------------------------------------------------------------------
// offset/mask conv as mma.sync implicit GEMM, k-major chunks. (unchanged R9)
// ---------------------------------------------------------------------------
__global__ __launch_bounds__(TPB, 4) void offc_mma_kernel(
    const uint32_t* __restrict__ xhl,
    const __nv_bfloat16* __restrict__ bwh,
    const __nv_bfloat16* __restrict__ bwl,
    const float* __restrict__ bias,
    float* __restrict__ om)
{
    extern __shared__ char smem[];
    const uint32_t sbu = smem_u32(smem);
    float* sbias = (float*)(smem + OS_BIAS);

    const int tid = threadIdx.x, wid = tid >> 5, lane = tid & 31;
    const int g = lane >> 2, tq = lane & 3;
    const int b = blockIdx.y;
    const int P0 = blockIdx.x * MT;

    if (tid < 32) sbias[tid] = (tid < OMC) ? bias[tid] : 0.f;

    const int pl = tid & 127, jh = tid >> 7;
    const int pg = P0 + pl;
    const int py = pg / Wv, px = pg - py*Wv;
    const uint32_t* srcB = xhl + (size_t)b*Cv*HWv + (size_t)(jh*32)*HWv;

    // ldmatrix lane geometry
    const int rowA = wid*16 + (lane & 15);
    const int kbA  = (lane & 16) ? 1 : 0;
    const int rowB0 = (lane & 7) + ((lane & 16) ? 8 : 0);
    const int kbB   = (lane & 8) ? 1 : 0;

    float acc[4][4];
    #pragma unroll
    for (int nt = 0; nt < 4; nt++)
        #pragma unroll
        for (int e = 0; e < 4; e++) acc[nt][e] = 0.f;

    for (int cc = 0; cc < NCH; cc++) {
        if (cc) __syncthreads();
        // stage B: 32 rows x 8 quads, hi/lo (uint4)
        {
            int idx = tid;
            int o = idx >> 3, cq = idx & 7;
            int gofs = o*CKK + cc*CKC + cq*8;
            uint32_t d = swz(o, cq);
            *(uint4*)(smem + OS_BH + d) = *(const uint4*)(bwh + gofs);
            *(uint4*)(smem + OS_BL + d) = *(const uint4*)(bwl + gofs);
        }
        // build A: fixed tap cc for the whole chunk
        {
            int yy = py + cc/3 - 1, xx = px + (cc % 3) - 1;
            bool val = ((unsigned)yy < (unsigned)Hv) && ((unsigned)xx < (unsigned)Wv);
            const uint32_t* p = srcB + yy*Wv + xx;
            #pragma unroll
            for (int q = 0; q < 4; q++) {
                uint32_t hq[4], lq[4];
                #pragma unroll
                for (int wi = 0; wi < 4; wi++) {
                    int c0 = 8*q + 2*wi;
                    uint32_t v0 = val ? __ldg(p + (size_t)c0*HWv) : 0u;
                    uint32_t v1 = val ? __ldg(p + (size_t)(c0+1)*HWv) : 0u;
                    hq[wi] = __byte_perm(v0, v1, 0x5410);
                    lq[wi] = __byte_perm(v0, v1, 0x7632);
                }
                uint32_t d = swz(pl, jh*4 + q);
                *(uint4*)(smem + OS_AH + d) = make_uint4(hq[0],hq[1],hq[2],hq[3]);
                *(uint4*)(smem + OS_AL + d) = make_uint4(lq[0],lq[1],lq[2],lq[3]);
            }
        }
        __syncthreads();
        // mma: 3 passes
        #pragma unroll
        for (int ks = 0; ks < 4; ks++) {
            uint32_t aAH = sbu + OS_AH + swz(rowA, ks*2 + kbA);
            uint32_t aH0,aH1,aH2,aH3, aL0,aL1,aL2,aL3;
            ldm_x4(aH0,aH1,aH2,aH3, aAH);
            ldm_x4(aL0,aL1,aL2,aL3, aAH + (OS_AL - OS_AH));
            uint32_t aB0 = sbu + OS_BH + swz(rowB0, ks*2 + kbB);
            uint32_t aB1 = sbu + OS_BH + swz(16 + rowB0, ks*2 + kbB);
            uint32_t bh0,bh1,bh2,bh3, bl0,bl1,bl2,bl3;
            ldm_x4(bh0,bh1,bh2,bh3, aB0);
            ldm_x4(bl0,bl1,bl2,bl3, aB0 + (OS_BL - OS_BH));
            mma_bf16(acc[0], aH0,aH1,aH2,aH3, bh0,bh1);
            mma_bf16(acc[0], aH0,aH1,aH2,aH3, bl0,bl1);
            mma_bf16(acc[0], aL0,aL1,aL2,aL3, bh0,bh1);
            mma_bf16(acc[1], aH0,aH1,aH2,aH3, bh2,bh3);
            mma_bf16(acc[1], aH0,aH1,aH2,aH3, bl2,bl3);
            mma_bf16(acc[1], aL0,aL1,aL2,aL3, bh2,bh3);
            ldm_x4(bh0,bh1,bh2,bh3, aB1);
            ldm_x4(bl0,bl1,bl2,bl3, aB1 + (OS_BL - OS_BH));
            mma_bf16(acc[2], aH0,aH1,aH2,aH3, bh0,bh1);
            mma_bf16(acc[2], aH0,aH1,aH2,aH3, bl0,bl1);
            mma_bf16(acc[2], aL0,aL1,aL2,aL3, bh0,bh1);
            mma_bf16(acc[3], aH0,aH1,aH2,aH3, bh2,bh3);
            mma_bf16(acc[3], aH0,aH1,aH2,aH3, bl2,bl3);
            mma_bf16(acc[3], aL0,aL1,aL2,aL3, bh2,bh3);
        }
    }

    // epilogue: +bias -> g_om
    #pragma unroll
    for (int nt = 0; nt < 4; nt++) {
        #pragma unroll
        for (int e = 0; e < 4; e++) {
            int o = nt*8 + 2*tq + (e & 1);
            if (o < OMC) {
                int p = P0 + wid*16 + g + (e >> 1)*8;
                om[((size_t)b*OMC + o)*HWv + p] = acc[nt][e] + sbias[o];
            }
        }
    }
}

// ---------------------------------------------------------------------------
// DCN via mma.sync bf16 3-pass + ldmatrix, k-major chunks. M=128, N=64.
// Warp tile 32px x 32o; gather tables computed inline per chunk.
// ---------------------------------------------------------------------------
__global__ __launch_bounds__(TPB, 3) void dcn_mma_kernel(
    const float* __restrict__ src,
    const __nv_bfloat16* __restrict__ wh,
    const __nv_bfloat16* __restrict__ wl,
    const float* __restrict__ bng,
    const float* __restrict__ bnb,
    const float* __restrict__ bnm,
    const float* __restrict__ bnv,
    const float* __restrict__ identity,
    float* __restrict__ out,
    uint32_t* __restrict__ midhl)
{
    extern __shared__ char smem[];
    const uint32_t sbu = smem_u32(smem);
    float*  sSc   = (float*)(smem + DS_SC);
    float*  sSh   = (float*)(smem + DS_SH);

    const int tid  = threadIdx.x, wid = tid >> 5, lane = tid & 31;
    const int g    = lane >> 2, tq = lane & 3;
    const int wq   = wid & 3, wn = wid >> 2;      // warp tile: 32px x 32o
    const int b    = blockIdx.y;
    const int P0   = blockIdx.x * MT;

    if (tid < 64) {
        float sc = bng[tid] * rsqrtf(bnv[tid] + 1e-5f);
        sSc[tid] = sc;
        sSh[tid] = bnb[tid] - bnm[tid]*sc;
    }
    __syncthreads();

    const int pl = tid & 127, jh = tid >> 7;
    const int pxg = P0 + pl;
    const int ppy = pxg / Wv, ppx = pxg - ppy*Wv;
    const float yq = (float)ppy - 1.f, xq = (float)ppx - 1.f;
    const float* omB  = g_om + (size_t)b*OMC*HWv + pxg;
    const float* srcB = src + (size_t)b*Cv*HWv + (size_t)jh*32*HWv;
    const float* srcC = src + (size_t)b*Cv*HWv;  // channel base (corner fallback uses same)

    // ldmatrix lane geometry
    const int laneA = lane & 15;
    const int kbA  = (lane & 16) ? 1 : 0;
    const int rowB0 = (lane & 7) + ((lane & 16) ? 8 : 0);
    const int kbB   = (lane & 8) ? 1 : 0;

    float acc[2][4][4];
    #pragma unroll
    for (int mt = 0; mt < 2; mt++)
        #pragma unroll
        for (int nt = 0; nt < 4; nt++)
            #pragma unroll
            for (int e = 0; e < 4; e++) acc[mt][nt][e] = 0.f;

    for (int cc = 0; cc < NCH; cc++) {
        if (cc) __syncthreads();

        // stage B chunk hi/lo: 64 rows x 8 quads (uint4)
        #pragma unroll
        for (int it = 0; it < 2; it++) {
            int idx = it*TPB + tid;
            int o = idx >> 3, cq = idx & 7;
            int gofs = o*CKK + cc*CKC + cq*8;
            uint32_t d = swz(o, cq);
            *(uint4*)(smem + DS_BH + d) = *(const uint4*)(wh + gofs);
            *(uint4*)(smem + DS_BL + d) = *(const uint4*)(wl + gofs);
        }

        // inline gather table for (cc, pl)
        {
            float dy = __ldg(omB + (size_t)(2*cc  )*HWv);
            float dx = __ldg(omB + (size_t)(2*cc+1)*HWv);
            float mr = __ldg(omB + (size_t)(18+cc )*HWv);
            float m  = 1.f / (1.f + expf(-mr));
            float pyf = yq + (float)(cc/3) + dy;
            float pxf = xq + (float)(cc%3) + dx;
            float yf = floorf(pyf), xf = floorf(pxf);
            float ly = pyf - yf, lx = pxf - xf;
            int iy0 = (int)yf, ix0 = (int)xf;
            float vy0 = ((unsigned)iy0     < (unsigned)Hv) ? 1.f : 0.f;
            float vy1 = ((unsigned)(iy0+1) < (unsigned)Hv) ? 1.f : 0.f;
            float vx0 = ((unsigned)ix0     < (unsigned)Wv) ? 1.f : 0.f;
            float vx1 = ((unsigned)(ix0+1) < (unsigned)Wv) ? 1.f : 0.f;
            float cwx = (1.f-ly)*(1.f-lx)*m*vy0*vx0;
            float cwy = (1.f-ly)*lx      *m*vy0*vx1;
            float cwz = ly      *(1.f-lx)*m*vy1*vx0;
            float cww = ly      *lx      *m*vy1*vx1;
            int iy0c = min(max(iy0,0),Hv-1), ix0c = min(max(ix0,0),Wv-1);
            int iy1c = iy0c + ((iy0 >= 0 && iy0 <= Hv-2) ? 1 : 0);
            int ix1c = ix0c + ((ix0 >= 0 && ix0 <= Wv-2) ? 1 : 0);

            const float* pA = srcB + iy0c*Wv + ix0c;
            const float* pB = srcB + iy0c*Wv + ix1c;
            const float* pC = srcB + iy1c*Wv + ix0c;
            const float* pD = srcB + iy1c*Wv + ix1c;
            #pragma unroll
            for (int q = 0; q < 4; q++) {
                uint32_t hq[4], lq[4];
                #pragma unroll
                for (int wi = 0; wi < 4; wi++) {
                    int c0 = 8*q + 2*wi;
                    float s0 = cwx*__ldg(pA + (size_t)c0*HWv) + cwy*__ldg(pB + (size_t)c0*HWv)
                             + cwz*__ldg(pC + (size_t)c0*HWv) + cww*__ldg(pD + (size_t)c0*HWv);
                    float s1 = cwx*__ldg(pA + (size_t)(c0+1)*HWv) + cwy*__ldg(pB + (size_t)(c0+1)*HWv)
                             + cwz*__ldg(pC + (size_t)(c0+1)*HWv) + cww*__ldg(pD + (size_t)(c0+1)*HWv);
                    uint32_t p0 = split_pack(s0), p1 = split_pack(s1);
                    hq[wi] = __byte_perm(p0, p1, 0x5410);
                    lq[wi] = __byte_perm(p0, p1, 0x7632);
                }
                uint32_t d = swz(pl, jh*4 + q);
                *(uint4*)(smem + DS_AH + d) = make_uint4(hq[0],hq[1],hq[2],hq[3]);
                *(uint4*)(smem + DS_AL + d) = make_uint4(lq[0],lq[1],lq[2],lq[3]);
            }
        }
        __syncthreads();

        // MMA: 4 k-steps; warp covers 32 px (2 m-tiles) x 32 o (2 n-pairs)
        #pragma unroll
        for (int ks = 0; ks < 4; ks++) {
            uint32_t aH[2][4], aL[2][4];
            #pragma unroll
            for (int mt = 0; mt < 2; mt++) {
                uint32_t aAH = sbu + DS_AH + swz(wq*32 + mt*16 + laneA, ks*2 + kbA);
                ldm_x4(aH[mt][0],aH[mt][1],aH[mt][2],aH[mt][3], aAH);
                ldm_x4(aL[mt][0],aL[mt][1],aL[mt][2],aL[mt][3], aAH + (DS_AL - DS_AH));
            }
            #pragma unroll
            for (int np = 0; np < 2; np++) {
                uint32_t aB = sbu + DS_BH + swz(wn*32 + np*16 + rowB0, ks*2 + kbB);
                uint32_t bh0,bh1,bh2,bh3, bl0,bl1,bl2,bl3;
                ldm_x4(bh0,bh1,bh2,bh3, aB);
                ldm_x4(bl0,bl1,bl2,bl3, aB + (DS_BL - DS_BH));
                #pragma unroll
                for (int mt = 0; mt < 2; mt++) {
                    mma_bf16(acc[mt][2*np],   aH[mt][0],aH[mt][1],aH[mt][2],aH[mt][3], bh0,bh1);
                    mma_bf16(acc[mt][2*np],   aH[mt][0],aH[mt][1],aH[mt][2],aH[mt][3], bl0,bl1);
                    mma_bf16(acc[mt][2*np],   aL[mt][0],aL[mt][1],aL[mt][2],aL[mt][3], bh0,bh1);
                    mma_bf16(acc[mt][2*np+1], aH[mt][0],aH[mt][1],aH[mt][2],aH[mt][3], bh2,bh3);
                    mma_bf16(acc[mt][2*np+1], aH[mt][0],aH[mt][1],aH[mt][2],aH[mt][3], bl2,bl3);
                    mma_bf16(acc[mt][2*np+1], aL[mt][0],aL[mt][1],aL[mt][2],aL[mt][3], bh2,bh3);
                }
            }
        }
    }

    // epilogue: BN (+residual) + exact GELU (+ mid hi/lo split for pass 1)
    const size_t bofs = (size_t)b*Cv*HWv;
    #pragma unroll
    for (int mt = 0; mt < 2; mt++) {
        const int px0 = P0 + wq*32 + mt*16 + g;
        #pragma unroll
        for (int nt = 0; nt < 4; nt++) {
            #pragma unroll
            for (int e = 0; e < 4; e++) {
                int o  = wn*32 + nt*8 + 2*tq + (e & 1);
                int px = px0 + (e >> 1)*8;
                float v = acc[mt][nt][e] * sSc[o] + sSh[o];
                size_t ofs = bofs + (size_t)o*HWv + px;
                if (identity) v += __ldg(identity + ofs);
                v = gelu_exact(v);
                out[ofs] = v;
                if (midhl) midhl[ofs] = split_pack(v);
            }
        }
    }
    (void)srcC;
}

// ---------------------------------------------------------------------------
extern "C" void kernel_launch(void* const* d_in, const int* in_sizes, int n_in,
                              void* d_out, int out_size)
{
    const float* x      = (const float*)d_in[0];
    const float* w_om1  = (const float*)d_in[1];
    const float* b_om1  = (const float*)d_in[2];
    const float* w_dcn1 = (const float*)d_in[3];
    const float* bn1g   = (const float*)d_in[4];
    const float* bn1b   = (const float*)d_in[5];
    const float* bn1m   = (const float*)d_in[6];
    const float* bn1v   = (const float*)d_in[7];
    const float* w_om2  = (const float*)d_in[8];
    const float* b_om2  = (const float*)d_in[9];
    const float* w_dcn2 = (const float*)d_in[10];
    const float* bn2g   = (const float*)d_in[11];
    const float* bn2b   = (const float*)d_in[12];
    const float* bn2m   = (const float*)d_in[13];
    const float* bn2v   = (const float*)d_in[14];
    float* out = (float*)d_out;

    float *om, *mid;
    uint32_t *xhl, *midhl;
    __nv_bfloat16 *wh1, *wl1, *wh2, *wl2, *omh1, *oml1, *omh2, *oml2;
    cudaGetSymbolAddress((void**)&om,    g_om);
    cudaGetSymbolAddress((void**)&mid,   g_mid);
    cudaGetSymbolAddress((void**)&xhl,   g_xhl);
    cudaGetSymbolAddress((void**)&midhl, g_midhl);
    cudaGetSymbolAddress((void**)&wh1,   g_wh1);
    cudaGetSymbolAddress((void**)&wl1,   g_wl1);
    cudaGetSymbolAddress((void**)&wh2,   g_wh2);
    cudaGetSymbolAddress((void**)&wl2,   g_wl2);
    cudaGetSymbolAddress((void**)&omh1,  g_omh1);
    cudaGetSymbolAddress((void**)&oml1,  g_oml1);
    cudaGetSymbolAddress((void**)&omh2,  g_omh2);
    cudaGetSymbolAddress((void**)&oml2,  g_oml2);

    cudaFuncSetAttribute(offc_mma_kernel, cudaFuncAttributeMaxDynamicSharedMemorySize, OS_TOT);
    cudaFuncSetAttribute(dcn_mma_kernel,  cudaFuncAttributeMaxDynamicSharedMemorySize, DS_TOT);

    prep_kernel<<<(Bv*Cv*HWv + 255)/256, 256>>>(x, w_dcn1, w_dcn2, w_om1, w_om2);

    dim3 grid(HWv/MT, Bv);   // 200 x 4

    offc_mma_kernel<<<grid, TPB, OS_TOT>>>(xhl, omh1, oml1, b_om1, om);
    dcn_mma_kernel<<<grid, TPB, DS_TOT>>>(x, wh1, wl1,
        bn1g, bn1b, bn1m, bn1v, nullptr, mid, midhl);

    offc_mma_kernel<<<grid, TPB, OS_TOT>>>(midhl, omh2, oml2, b_om2, om);
    dcn_mma_kernel<<<grid, TPB, DS_TOT>>>(mid, wh2, wl2,
        bn2g, bn2b, bn2m, bn2v, x, out, nullptr);
}

// round 11
// speedup vs baseline: 1.3554x; 1.3554x over previous
#include <cuda_runtime.h>
#include <cuda_bf16.h>
#include <math.h>
#include <stdint.h>

#define Bv   4
#define Cv   64
#define Hv   160
#define Wv   160
#define HWv  25600
#define KKv  9
#define OMC  27
#define CKK  576

#define MT    128          // px per block tile (M)
#define TPB   256
#define CKC   64           // K chunk = one kernel tap (64 channels)
#define NCH   9

// swizzled tile: row = 128B = 8 uint4; quad col stored at (cq ^ (row&7))

// dcn smem offsets (bytes)
#define DS_WGT  0          // float4[1152] 18432
#define DS_BASE 18432      // int[1152]     4608
#define DS_SC   23040      // float[64]
#define DS_SH   23296      // float[64]
#define DS_AH   23552      // 128*128 = 16384
#define DS_AL   39936      // 16384
#define DS_BH   56320      // 64*128 = 8192
#define DS_BL   64512      // 8192
#define DS_TOT  72704

// offc smem offsets
#define OS_AH   0          // 16384
#define OS_AL   16384      // 16384
#define OS_BH   32768      // 32*128 = 4096
#define OS_BL   36864      // 4096
#define OS_BIAS 40960      // 128
#define OS_TOT  41088

// scratch
__device__ float    g_om[Bv*OMC*HWv];
__device__ float    g_mid[Bv*Cv*HWv];
__device__ uint32_t g_xhl[Bv*Cv*HWv];     // packed (bf16 hi | bf16 lo<<16)
__device__ uint32_t g_midhl[Bv*Cv*HWv];
// k-major weights: [o][k*64 + c]
__device__ __align__(16) __nv_bfloat16 g_wh1[Cv*CKK], g_wl1[Cv*CKK];
__device__ __align__(16) __nv_bfloat16 g_wh2[Cv*CKK], g_wl2[Cv*CKK];
__device__ __align__(16) __nv_bfloat16 g_omh1[32*CKK], g_oml1[32*CKK];
__device__ __align__(16) __nv_bfloat16 g_omh2[32*CKK], g_oml2[32*CKK];

__device__ __forceinline__ float gelu_exact(float v) {
    return 0.5f * v * (1.0f + erff(v * 0.70710678118654752f));
}
__device__ __forceinline__ uint32_t split_pack(float v) {
    __nv_bfloat16 h = __float2bfloat16(v);
    __nv_bfloat16 l = __float2bfloat16(v - __bfloat162float(h));
    return (uint32_t)__bfloat16_as_ushort(h) | ((uint32_t)__bfloat16_as_ushort(l) << 16);
}
__device__ __forceinline__ uint32_t smem_u32(const void* p) {
    uint32_t a;
    asm("{ .reg .u64 t; cvta.to.shared.u64 t, %1; cvt.u32.u64 %0, t; }" : "=r"(a) : "l"(p));
    return a;
}
__device__ __forceinline__ void mma_bf16(float* d,
    uint32_t a0, uint32_t a1, uint32_t a2, uint32_t a3, uint32_t b0, uint32_t b1)
{
    asm volatile(
        "mma.sync.aligned.m16n8k16.row.col.f32.bf16.bf16.f32 "
        "{%0,%1,%2,%3},{%4,%5,%6,%7},{%8,%9},{%0,%1,%2,%3};"
        : "+f"(d[0]), "+f"(d[1]), "+f"(d[2]), "+f"(d[3])
        : "r"(a0), "r"(a1), "r"(a2), "r"(a3), "r"(b0), "r"(b1));
}
__device__ __forceinline__ void ldm_x4(uint32_t& r0, uint32_t& r1, uint32_t& r2, uint32_t& r3, uint32_t addr) {
    asm volatile("ldmatrix.sync.aligned.m8n8.x4.shared.b16 {%0,%1,%2,%3}, [%4];"
                 : "=r"(r0), "=r"(r1), "=r"(r2), "=r"(r3) : "r"(addr));
}
// swizzled byte offset within a tile: row (128B rows), quad column cq
__device__ __forceinline__ uint32_t swz(int row, int cq) {
    return (uint32_t)(row*128 + ((cq ^ (row & 7)) << 4));
}

// ---------------------------------------------------------------------------
// prep: split to bf16 hi/lo; weights permuted to k-major [o][k*64+c]
// ---------------------------------------------------------------------------
__global__ void prep_kernel(const float* __restrict__ x,
                            const float* __restrict__ wd1, const float* __restrict__ wd2,
                            const float* __restrict__ wom1, const float* __restrict__ wom2)
{
    int i = blockIdx.x * 256 + threadIdx.x;
    if (i < Bv*Cv*HWv) g_xhl[i] = split_pack(x[i]);
    if (i < Cv*CKK) {
        int o = i / CKK, r = i - o*CKK;
        int c = r / 9, k = r - 9*c;
        int dst = o*CKK + k*64 + c;
        float v1 = wd1[i];
        __nv_bfloat16 h1 = __float2bfloat16(v1);
        g_wh1[dst] = h1;
        g_wl1[dst] = __float2bfloat16(v1 - __bfloat162float(h1));
        float v2 = wd2[i];
        __nv_bfloat16 h2 = __float2bfloat16(v2);
        g_wh2[dst] = h2;
        g_wl2[dst] = __float2bfloat16(v2 - __bfloat162float(h2));
    }
    if (i < 32*CKK) {
        int o = i / CKK, r = i - o*CKK;
        int c = r / 9, k = r - 9*c;
        int dst = o*CKK + k*64 + c;
        float v1 = (i < OMC*CKK) ? wom1[i] : 0.f;
        __nv_bfloat16 h1 = __float2bfloat16(v1);
        g_omh1[dst] = h1;
        g_oml1[dst] = __float2bfloat16(v1 - __bfloat162float(h1));
        float v2 = (i < OMC*CKK) ? wom2[i] : 0.f;
        __nv_bfloat16 h2 = __float2bfloat16(v2);
        g_omh2[dst] = h2;
        g_oml2[dst] = __float2bfloat16(v2 - __bfloat162float(h2));
    }
}

// ---------------------------------------------------------------------------
// offset/mask conv as mma.sync implicit GEMM, k-major chunks. (unchanged R9)
// ---------------------------------------------------------------------------
__global__ __launch_bounds__(TPB, 4) void offc_mma_kernel(
    const uint32_t* __restrict__ xhl,
    const __nv_bfloat16* __restrict__ bwh,
    const __nv_bfloat16* __restrict__ bwl,
    const float* __restrict__ bias,
    float* __restrict__ om)
{
    extern __shared__ char smem[];
    const uint32_t sbu = smem_u32(smem);
    float* sbias = (float*)(smem + OS_BIAS);

    const int tid = threadIdx.x, wid = tid >> 5, lane = tid & 31;
    const int g = lane >> 2, tq = lane & 3;
    const int b = blockIdx.y;
    const int P0 = blockIdx.x * MT;

    if (tid < 32) sbias[tid] = (tid < OMC) ? bias[tid] : 0.f;

    const int pl = tid & 127, jh = tid >> 7;
    const int pg = P0 + pl;
    const int py = pg / Wv, px = pg - py*Wv;
    const uint32_t* srcB = xhl + (size_t)b*Cv*HWv + (size_t)(jh*32)*HWv;

    // ldmatrix lane geometry
    const int rowA = wid*16 + (lane & 15);
    const int kbA  = (lane & 16) ? 1 : 0;
    const int rowB0 = (lane & 7) + ((lane & 16) ? 8 : 0);
    const int kbB   = (lane & 8) ? 1 : 0;

    float acc[4][4];
    #pragma unroll
    for (int nt = 0; nt < 4; nt++)
        #pragma unroll
        for (int e = 0; e < 4; e++) acc[nt][e] = 0.f;

    for (int cc = 0; cc < NCH; cc++) {
        if (cc) __syncthreads();
        // stage B: 32 rows x 8 quads, hi/lo (uint4)
        {
            int idx = tid;
            int o = idx >> 3, cq = idx & 7;
            int gofs = o*CKK + cc*CKC + cq*8;
            uint32_t d = swz(o, cq);
            *(uint4*)(smem + OS_BH + d) = *(const uint4*)(bwh + gofs);
            *(uint4*)(smem + OS_BL + d) = *(const uint4*)(bwl + gofs);
        }
        // build A: fixed tap cc for the whole chunk
        {
            int yy = py + cc/3 - 1, xx = px + (cc % 3) - 1;
            bool val = ((unsigned)yy < (unsigned)Hv) && ((unsigned)xx < (unsigned)Wv);
            const uint32_t* p = srcB + yy*Wv + xx;
            #pragma unroll
            for (int q = 0; q < 4; q++) {
                uint32_t hq[4], lq[4];
                #pragma unroll
                for (int wi = 0; wi < 4; wi++) {
                    int c0 = 8*q + 2*wi;
                    uint32_t v0 = val ? __ldg(p + (size_t)c0*HWv) : 0u;
                    uint32_t v1 = val ? __ldg(p + (size_t)(c0+1)*HWv) : 0u;
                    hq[wi] = __byte_perm(v0, v1, 0x5410);
                    lq[wi] = __byte_perm(v0, v1, 0x7632);
                }
                uint32_t d = swz(pl, jh*4 + q);
                *(uint4*)(smem + OS_AH + d) = make_uint4(hq[0],hq[1],hq[2],hq[3]);
                *(uint4*)(smem + OS_AL + d) = make_uint4(lq[0],lq[1],lq[2],lq[3]);
            }
        }
        __syncthreads();
        // mma: 3 passes
        #pragma unroll
        for (int ks = 0; ks < 4; ks++) {
            uint32_t aAH = sbu + OS_AH + swz(rowA, ks*2 + kbA);
            uint32_t aH0,aH1,aH2,aH3, aL0,aL1,aL2,aL3;
            ldm_x4(aH0,aH1,aH2,aH3, aAH);
            ldm_x4(aL0,aL1,aL2,aL3, aAH + (OS_AL - OS_AH));
            uint32_t aB0 = sbu + OS_BH + swz(rowB0, ks*2 + kbB);
            uint32_t aB1 = sbu + OS_BH + swz(16 + rowB0, ks*2 + kbB);
            uint32_t bh0,bh1,bh2,bh3, bl0,bl1,bl2,bl3;
            ldm_x4(bh0,bh1,bh2,bh3, aB0);
            ldm_x4(bl0,bl1,bl2,bl3, aB0 + (OS_BL - OS_BH));
            mma_bf16(acc[0], aH0,aH1,aH2,aH3, bh0,bh1);
            mma_bf16(acc[0], aH0,aH1,aH2,aH3, bl0,bl1);
            mma_bf16(acc[0], aL0,aL1,aL2,aL3, bh0,bh1);
            mma_bf16(acc[1], aH0,aH1,aH2,aH3, bh2,bh3);
            mma_bf16(acc[1], aH0,aH1,aH2,aH3, bl2,bl3);
            mma_bf16(acc[1], aL0,aL1,aL2,aL3, bh2,bh3);
            ldm_x4(bh0,bh1,bh2,bh3, aB1);
            ldm_x4(bl0,bl1,bl2,bl3, aB1 + (OS_BL - OS_BH));
            mma_bf16(acc[2], aH0,aH1,aH2,aH3, bh0,bh1);
            mma_bf16(acc[2], aH0,aH1,aH2,aH3, bl0,bl1);
            mma_bf16(acc[2], aL0,aL1,aL2,aL3, bh0,bh1);
            mma_bf16(acc[3], aH0,aH1,aH2,aH3, bh2,bh3);
            mma_bf16(acc[3], aH0,aH1,aH2,aH3, bl2,bl3);
            mma_bf16(acc[3], aL0,aL1,aL2,aL3, bh2,bh3);
        }
    }

    // epilogue: +bias -> g_om
    #pragma unroll
    for (int nt = 0; nt < 4; nt++) {
        #pragma unroll
        for (int e = 0; e < 4; e++) {
            int o = nt*8 + 2*tq + (e & 1);
            if (o < OMC) {
                int p = P0 + wid*16 + g + (e >> 1)*8;
                om[((size_t)b*OMC + o)*HWv + p] = acc[nt][e] + sbias[o];
            }
        }
    }
}

// ---------------------------------------------------------------------------
// DCN via mma.sync bf16 3-pass + ldmatrix, k-major chunks. M=128, N=64.
// R9 structure; gather loads batched per quad for MLP.
// ---------------------------------------------------------------------------
__global__ __launch_bounds__(TPB, 3) void dcn_mma_kernel(
    const float* __restrict__ src,
    const __nv_bfloat16* __restrict__ wh,
    const __nv_bfloat16* __restrict__ wl,
    const float* __restrict__ bng,
    const float* __restrict__ bnb,
    const float* __restrict__ bnm,
    const float* __restrict__ bnv,
    const float* __restrict__ identity,
    float* __restrict__ out,
    uint32_t* __restrict__ midhl)
{
    extern __shared__ char smem[];
    const uint32_t sbu = smem_u32(smem);
    float4* sWgt  = (float4*)(smem + DS_WGT);
    int*    sBase = (int*)(smem + DS_BASE);
    float*  sSc   = (float*)(smem + DS_SC);
    float*  sSh   = (float*)(smem + DS_SH);

    const int tid  = threadIdx.x, wid = tid >> 5, lane = tid & 31;
    const int g    = lane >> 2, tq = lane & 3;
    const int b    = blockIdx.y;
    const int P0   = blockIdx.x * MT;

    if (tid < 64) {
        float sc = bng[tid] * rsqrtf(bnv[tid] + 1e-5f);
        sSc[tid] = sc;
        sSh[tid] = bnb[tid] - bnm[tid]*sc;
    }

    // gather tables: 9 k x 128 px
    const float* omB = g_om + (size_t)b*OMC*HWv;
    for (int idx = tid; idx < KKv*MT; idx += TPB) {
        int k = idx >> 7, pl = idx & 127;
        int pxg = P0 + pl;
        int y = pxg / Wv, x = pxg - y*Wv;
        float dy = omB[(2*k  )*HWv + pxg];
        float dx = omB[(2*k+1)*HWv + pxg];
        float mr = omB[(18+k )*HWv + pxg];
        float m  = 1.f / (1.f + expf(-mr));
        float pyf = (float)y - 1.f + (float)(k/3) + dy;
        float pxf = (float)x - 1.f + (float)(k%3) + dx;
        float yf = floorf(pyf), xf = floorf(pxf);
        float ly = pyf - yf, lx = pxf - xf;
        int iy0 = (int)yf, ix0 = (int)xf;
        float vy0 = ((unsigned)iy0     < (unsigned)Hv) ? 1.f : 0.f;
        float vy1 = ((unsigned)(iy0+1) < (unsigned)Hv) ? 1.f : 0.f;
        float vx0 = ((unsigned)ix0     < (unsigned)Wv) ? 1.f : 0.f;
        float vx1 = ((unsigned)(ix0+1) < (unsigned)Wv) ? 1.f : 0.f;
        sWgt[idx] = make_float4((1.f-ly)*(1.f-lx)*m*vy0*vx0,
                                (1.f-ly)*lx      *m*vy0*vx1,
                                ly      *(1.f-lx)*m*vy1*vx0,
                                ly      *lx      *m*vy1*vx1);
        int iy0c = min(max(iy0,0),Hv-1), ix0c = min(max(ix0,0),Wv-1);
        int dy1 = (iy0 >= 0 && iy0 <= Hv-2) ? 1 : 0;
        int dx1 = (ix0 >= 0 && ix0 <= Wv-2) ? 1 : 0;
        sBase[idx] = iy0c | (ix0c<<8) | (dy1<<16) | (dx1<<17);
    }
    __syncthreads();

    const float* srcB = src + (size_t)b*Cv*HWv + (size_t)(tid >> 7)*32*HWv;
    const int pl = tid & 127, jh = tid >> 7;

    // ldmatrix lane geometry
    const int rowA = wid*16 + (lane & 15);
    const int kbA  = (lane & 16) ? 1 : 0;
    const int rowB0 = (lane & 7) + ((lane & 16) ? 8 : 0);
    const int kbB   = (lane & 8) ? 1 : 0;

    float acc[8][4];
    #pragma unroll
    for (int nt = 0; nt < 8; nt++)
        #pragma unroll
        for (int e = 0; e < 4; e++) acc[nt][e] = 0.f;

    for (int cc = 0; cc < NCH; cc++) {
        if (cc) __syncthreads();

        // stage B chunk hi/lo: 64 rows x 8 quads (uint4)
        #pragma unroll
        for (int it = 0; it < 2; it++) {
            int idx = it*TPB + tid;
            int o = idx >> 3, cq = idx & 7;
            int gofs = o*CKK + cc*CKC + cq*8;
            uint32_t d = swz(o, cq);
            *(uint4*)(smem + DS_BH + d) = *(const uint4*)(wh + gofs);
            *(uint4*)(smem + DS_BL + d) = *(const uint4*)(wl + gofs);
        }

        // sample A chunk: fixed tap cc; batched corner loads for MLP
        {
            int gi = cc*MT + pl;
            float4 cw = sWgt[gi];
            int ev = sBase[gi];
            int iy0 = ev & 255, ix0 = (ev>>8) & 255;
            int iy1 = iy0 + ((ev>>16)&1), ix1 = ix0 + ((ev>>17)&1);
            const float* pA = srcB + iy0*Wv + ix0;
            const float* pB = srcB + iy0*Wv + ix1;
            const float* pC = srcB + iy1*Wv + ix0;
            const float* pD = srcB + iy1*Wv + ix1;
            #pragma unroll
            for (int q = 0; q < 4; q++) {
                // batch all 32 corner loads for this quad before any math
                float vA[8], vB[8], vC[8], vD[8];
                #pragma unroll
                for (int ci = 0; ci < 8; ci++) {
                    size_t co = (size_t)(8*q + ci)*HWv;
                    vA[ci] = __ldg(pA + co);
                    vB[ci] = __ldg(pB + co);
                    vC[ci] = __ldg(pC + co);
                    vD[ci] = __ldg(pD + co);
                }
                uint32_t hq[4], lq[4];
                #pragma unroll
                for (int wi = 0; wi < 4; wi++) {
                    float s0 = cw.x*vA[2*wi]   + cw.y*vB[2*wi]
                             + cw.z*vC[2*wi]   + cw.w*vD[2*wi];
                    float s1 = cw.x*vA[2*wi+1] + cw.y*vB[2*wi+1]
                             + cw.z*vC[2*wi+1] + cw.w*vD[2*wi+1];
                    uint32_t p0 = split_pack(s0), p1 = split_pack(s1);
                    hq[wi] = __byte_perm(p0, p1, 0x5410);
                    lq[wi] = __byte_perm(p0, p1, 0x7632);
                }
                uint32_t d = swz(pl, jh*4 + q);
                *(uint4*)(smem + DS_AH + d) = make_uint4(hq[0],hq[1],hq[2],hq[3]);
                *(uint4*)(smem + DS_AL + d) = make_uint4(lq[0],lq[1],lq[2],lq[3]);
            }
        }
        __syncthreads();

        // MMA: 4 k-steps x 8 n-tiles x 3 passes
        #pragma unroll
        for (int ks = 0; ks < 4; ks++) {
            uint32_t aAH = sbu + DS_AH + swz(rowA, ks*2 + kbA);
            uint32_t aH0,aH1,aH2,aH3, aL0,aL1,aL2,aL3;
            ldm_x4(aH0,aH1,aH2,aH3, aAH);
            ldm_x4(aL0,aL1,aL2,aL3, aAH + (DS_AL - DS_AH));
            #pragma unroll
            for (int np = 0; np < 4; np++) {
                uint32_t aB = sbu + DS_BH + swz(np*16 + rowB0, ks*2 + kbB);
                uint32_t bh0,bh1,bh2,bh3, bl0,bl1,bl2,bl3;
                ldm_x4(bh0,bh1,bh2,bh3, aB);
                ldm_x4(bl0,bl1,bl2,bl3, aB + (DS_BL - DS_BH));
                mma_bf16(acc[2*np],   aH0,aH1,aH2,aH3, bh0,bh1);
                mma_bf16(acc[2*np],   aH0,aH1,aH2,aH3, bl0,bl1);
                mma_bf16(acc[2*np],   aL0,aL1,aL2,aL3, bh0,bh1);
                mma_bf16(acc[2*np+1], aH0,aH1,aH2,aH3, bh2,bh3);
                mma_bf16(acc[2*np+1], aH0,aH1,aH2,aH3, bl2,bl3);
                mma_bf16(acc[2*np+1], aL0,aL1,aL2,aL3, bh2,bh3);
            }
        }
    }

    // epilogue: BN (+residual) + exact GELU (+ mid hi/lo split for pass 1)
    const int px0 = P0 + wid*16 + g;
    const size_t bofs = (size_t)b*Cv*HWv;
    #pragma unroll
    for (int nt = 0; nt < 8; nt++) {
        #pragma unroll
        for (int e = 0; e < 4; e++) {
            int o  = nt*8 + 2*tq + (e & 1);
            int px = px0 + (e >> 1)*8;
            float v = acc[nt][e] * sSc[o] + sSh[o];
            size_t ofs = bofs + (size_t)o*HWv + px;
            if (identity) v += __ldg(identity + ofs);
            v = gelu_exact(v);
            out[ofs] = v;
            if (midhl) midhl[ofs] = split_pack(v);
        }
    }
}

// ---------------------------------------------------------------------------
extern "C" void kernel_launch(void* const* d_in, const int* in_sizes, int n_in,
                              void* d_out, int out_size)
{
    const float* x      = (const float*)d_in[0];
    const float* w_om1  = (const float*)d_in[1];
    const float* b_om1  = (const float*)d_in[2];
    const float* w_dcn1 = (const float*)d_in[3];
    const float* bn1g   = (const float*)d_in[4];
    const float* bn1b   = (const float*)d_in[5];
    const float* bn1m   = (const float*)d_in[6];
    const float* bn1v   = (const float*)d_in[7];
    const float* w_om2  = (const float*)d_in[8];
    const float* b_om2  = (const float*)d_in[9];
    const float* w_dcn2 = (const float*)d_in[10];
    const float* bn2g   = (const float*)d_in[11];
    const float* bn2b   = (const float*)d_in[12];
    const float* bn2m   = (const float*)d_in[13];
    const float* bn2v   = (const float*)d_in[14];
    float* out = (float*)d_out;

    float *om, *mid;
    uint32_t *xhl, *midhl;
    __nv_bfloat16 *wh1, *wl1, *wh2, *wl2, *omh1, *oml1, *omh2, *oml2;
    cudaGetSymbolAddress((void**)&om,    g_om);
    cudaGetSymbolAddress((void**)&mid,   g_mid);
    cudaGetSymbolAddress((void**)&xhl,   g_xhl);
    cudaGetSymbolAddress((void**)&midhl, g_midhl);
    cudaGetSymbolAddress((void**)&wh1,   g_wh1);
    cudaGetSymbolAddress((void**)&wl1,   g_wl1);
    cudaGetSymbolAddress((void**)&wh2,   g_wh2);
    cudaGetSymbolAddress((void**)&wl2,   g_wl2);
    cudaGetSymbolAddress((void**)&omh1,  g_omh1);
    cudaGetSymbolAddress((void**)&oml1,  g_oml1);
    cudaGetSymbolAddress((void**)&omh2,  g_omh2);
    cudaGetSymbolAddress((void**)&oml2,  g_oml2);

    cudaFuncSetAttribute(offc_mma_kernel, cudaFuncAttributeMaxDynamicSharedMemorySize, OS_TOT);
    cudaFuncSetAttribute(dcn_mma_kernel,  cudaFuncAttributeMaxDynamicSharedMemorySize, DS_TOT);

    prep_kernel<<<(Bv*Cv*HWv + 255)/256, 256>>>(x, w_dcn1, w_dcn2, w_om1, w_om2);

    dim3 grid(HWv/MT, Bv);   // 200 x 4

    offc_mma_kernel<<<grid, TPB, OS_TOT>>>(xhl, omh1, oml1, b_om1, om);
    dcn_mma_kernel<<<grid, TPB, DS_TOT>>>(x, wh1, wl1,
        bn1g, bn1b, bn1m, bn1v, nullptr, mid, midhl);

    offc_mma_kernel<<<grid, TPB, OS_TOT>>>(midhl, omh2, oml2, b_om2, om);
    dcn_mma_kernel<<<grid, TPB, DS_TOT>>>(mid, wh2, wl2,
        bn2g, bn2b, bn2m, bn2v, x, out, nullptr);
}

// round 12
// speedup vs baseline: 1.4086x; 1.0392x over previous
#include <cuda_runtime.h>
#include <cuda_bf16.h>
#include <math.h>
#include <stdint.h>

#define Bv   4
#define Cv   64
#define Hv   160
#define Wv   160
#define HWv  25600
#define KKv  9
#define OMC  27
#define CKK  576

#define MT    128          // px per block tile (M)
#define TPB   256
#define CKC   64           // K chunk = one kernel tap (64 channels)
#define NCH   9

// swizzled tile: row = 128B = 8 uint4; quad col stored at (cq ^ (row&7))

// fused smem map (bytes). A/B tile regions are reused by both phases;
// om buffer overlaps the AH region (dead between offc-MMA end and sampling).
#define FS_SC    0          // float[64]
#define FS_SH    256        // float[64]
#define FS_BIAS  512        // float[32]
#define FS_WGT   1024       // float4[1152] = 18432 -> [1024, 19456)
#define FS_BASE  19456      // int[1152]    =  4608 -> [19456, 24064)
#define FS_AH    24576      // 16384
#define FS_AL    40960      // 16384
#define FS_BH    57344      // 8192
#define FS_BL    65536      // 8192
#define FS_OM    24576      // float[128*29] = 14848 (overlaps AH region)
#define OMST     29         // om row stride (words), conflict-free
#define FS_TOT   73728

// scratch
__device__ float    g_mid[Bv*Cv*HWv];
__device__ uint32_t g_xhl[Bv*Cv*HWv];     // packed (bf16 hi | bf16 lo<<16)
__device__ uint32_t g_midhl[Bv*Cv*HWv];
// k-major weights: [o][k*64 + c]
__device__ __align__(16) __nv_bfloat16 g_wh1[Cv*CKK], g_wl1[Cv*CKK];
__device__ __align__(16) __nv_bfloat16 g_wh2[Cv*CKK], g_wl2[Cv*CKK];
__device__ __align__(16) __nv_bfloat16 g_omh1[32*CKK], g_oml1[32*CKK];
__device__ __align__(16) __nv_bfloat16 g_omh2[32*CKK], g_oml2[32*CKK];

__device__ __forceinline__ float gelu_exact(float v) {
    return 0.5f * v * (1.0f + erff(v * 0.70710678118654752f));
}
__device__ __forceinline__ uint32_t split_pack(float v) {
    __nv_bfloat16 h = __float2bfloat16(v);
    __nv_bfloat16 l = __float2bfloat16(v - __bfloat162float(h));
    return (uint32_t)__bfloat16_as_ushort(h) | ((uint32_t)__bfloat16_as_ushort(l) << 16);
}
__device__ __forceinline__ uint32_t smem_u32(const void* p) {
    uint32_t a;
    asm("{ .reg .u64 t; cvta.to.shared.u64 t, %1; cvt.u32.u64 %0, t; }" : "=r"(a) : "l"(p));
    return a;
}
__device__ __forceinline__ void mma_bf16(float* d,
    uint32_t a0, uint32_t a1, uint32_t a2, uint32_t a3, uint32_t b0, uint32_t b1)
{
    asm volatile(
        "mma.sync.aligned.m16n8k16.row.col.f32.bf16.bf16.f32 "
        "{%0,%1,%2,%3},{%4,%5,%6,%7},{%8,%9},{%0,%1,%2,%3};"
        : "+f"(d[0]), "+f"(d[1]), "+f"(d[2]), "+f"(d[3])
        : "r"(a0), "r"(a1), "r"(a2), "r"(a3), "r"(b0), "r"(b1));
}
__device__ __forceinline__ void ldm_x4(uint32_t& r0, uint32_t& r1, uint32_t& r2, uint32_t& r3, uint32_t addr) {
    asm volatile("ldmatrix.sync.aligned.m8n8.x4.shared.b16 {%0,%1,%2,%3}, [%4];"
                 : "=r"(r0), "=r"(r1), "=r"(r2), "=r"(r3) : "r"(addr));
}
__device__ __forceinline__ uint32_t swz(int row, int cq) {
    return (uint32_t)(row*128 + ((cq ^ (row & 7)) << 4));
}

// ---------------------------------------------------------------------------
// prep: split to bf16 hi/lo; weights permuted to k-major [o][k*64+c]
// ---------------------------------------------------------------------------
__global__ void prep_kernel(const float* __restrict__ x,
                            const float* __restrict__ wd1, const float* __restrict__ wd2,
                            const float* __restrict__ wom1, const float* __restrict__ wom2)
{
    int i = blockIdx.x * 256 + threadIdx.x;
    if (i < Bv*Cv*HWv) g_xhl[i] = split_pack(x[i]);
    if (i < Cv*CKK) {
        int o = i / CKK, r = i - o*CKK;
        int c = r / 9, k = r - 9*c;
        int dst = o*CKK + k*64 + c;
        float v1 = wd1[i];
        __nv_bfloat16 h1 = __float2bfloat16(v1);
        g_wh1[dst] = h1;
        g_wl1[dst] = __float2bfloat16(v1 - __bfloat162float(h1));
        float v2 = wd2[i];
        __nv_bfloat16 h2 = __float2bfloat16(v2);
        g_wh2[dst] = h2;
        g_wl2[dst] = __float2bfloat16(v2 - __bfloat162float(h2));
    }
    if (i < 32*CKK) {
        int o = i / CKK, r = i - o*CKK;
        int c = r / 9, k = r - 9*c;
        int dst = o*CKK + k*64 + c;
        float v1 = (i < OMC*CKK) ? wom1[i] : 0.f;
        __nv_bfloat16 h1 = __float2bfloat16(v1);
        g_omh1[dst] = h1;
        g_oml1[dst] = __float2bfloat16(v1 - __bfloat162float(h1));
        float v2 = (i < OMC*CKK) ? wom2[i] : 0.f;
        __nv_bfloat16 h2 = __float2bfloat16(v2);
        g_omh2[dst] = h2;
        g_oml2[dst] = __float2bfloat16(v2 - __bfloat162float(h2));
    }
}

// ---------------------------------------------------------------------------
// Fused BasicBlock half: offc (mma) -> om in smem -> tables -> dcn (mma)
// ---------------------------------------------------------------------------
__global__ __launch_bounds__(TPB, 3) void fused_kernel(
    const uint32_t* __restrict__ xhl_in,      // offc input, packed hi/lo
    const __nv_bfloat16* __restrict__ omwh,   // offc weights hi  [32][576] k-major
    const __nv_bfloat16* __restrict__ omwl,   // offc weights lo
    const float* __restrict__ ombias,
    const float* __restrict__ src,            // dcn gather source (fp32)
    const __nv_bfloat16* __restrict__ wh,     // dcn weights hi [64][576] k-major
    const __nv_bfloat16* __restrict__ wl,
    const float* __restrict__ bng,
    const float* __restrict__ bnb,
    const float* __restrict__ bnm,
    const float* __restrict__ bnv,
    const float* __restrict__ identity,
    float* __restrict__ out,
    uint32_t* __restrict__ midhl)
{
    extern __shared__ char smem[];
    const uint32_t sbu = smem_u32(smem);
    float*  sSc   = (float*)(smem + FS_SC);
    float*  sSh   = (float*)(smem + FS_SH);
    float*  sbias = (float*)(smem + FS_BIAS);
    float4* sWgt  = (float4*)(smem + FS_WGT);
    int*    sBase = (int*)(smem + FS_BASE);
    float*  sOm   = (float*)(smem + FS_OM);

    const int tid  = threadIdx.x, wid = tid >> 5, lane = tid & 31;
    const int g    = lane >> 2, tq = lane & 3;
    const int b    = blockIdx.y;
    const int P0   = blockIdx.x * MT;

    if (tid < 64) {
        float sc = bng[tid] * rsqrtf(bnv[tid] + 1e-5f);
        sSc[tid] = sc;
        sSh[tid] = bnb[tid] - bnm[tid]*sc;
    } else if (tid < 96) {
        int o = tid - 64;
        sbias[o] = (o < OMC) ? ombias[o] : 0.f;
    }

    const int pl = tid & 127, jh = tid >> 7;
    const int pg = P0 + pl;
    const int py = pg / Wv, px = pg - py*Wv;

    // ldmatrix lane geometry (shared by both phases)
    const int rowA = wid*16 + (lane & 15);
    const int kbA  = (lane & 16) ? 1 : 0;
    const int rowB0 = (lane & 7) + ((lane & 16) ? 8 : 0);
    const int kbB   = (lane & 8) ? 1 : 0;

    // ================= Phase 1: offset/mask conv (M=128, N=32) =================
    {
        const uint32_t* srcO = xhl_in + (size_t)b*Cv*HWv + (size_t)(jh*32)*HWv;
        float acc[4][4];
        #pragma unroll
        for (int nt = 0; nt < 4; nt++)
            #pragma unroll
            for (int e = 0; e < 4; e++) acc[nt][e] = 0.f;

        for (int cc = 0; cc < NCH; cc++) {
            if (cc) __syncthreads();
            // stage B: 32 rows x 8 quads hi/lo
            {
                int o = tid >> 3, cq = tid & 7;
                int gofs = o*CKK + cc*CKC + cq*8;
                uint32_t d = swz(o, cq);
                *(uint4*)(smem + FS_BH + d) = *(const uint4*)(omwh + gofs);
                *(uint4*)(smem + FS_BL + d) = *(const uint4*)(omwl + gofs);
            }
            // build A: fixed tap cc
            {
                int yy = py + cc/3 - 1, xx = px + (cc % 3) - 1;
                bool val = ((unsigned)yy < (unsigned)Hv) && ((unsigned)xx < (unsigned)Wv);
                const uint32_t* p = srcO + yy*Wv + xx;
                #pragma unroll
                for (int q = 0; q < 4; q++) {
                    uint32_t hq[4], lq[4];
                    #pragma unroll
                    for (int wi = 0; wi < 4; wi++) {
                        int c0 = 8*q + 2*wi;
                        uint32_t v0 = val ? __ldg(p + (size_t)c0*HWv) : 0u;
                        uint32_t v1 = val ? __ldg(p + (size_t)(c0+1)*HWv) : 0u;
                        hq[wi] = __byte_perm(v0, v1, 0x5410);
                        lq[wi] = __byte_perm(v0, v1, 0x7632);
                    }
                    uint32_t d = swz(pl, jh*4 + q);
                    *(uint4*)(smem + FS_AH + d) = make_uint4(hq[0],hq[1],hq[2],hq[3]);
                    *(uint4*)(smem + FS_AL + d) = make_uint4(lq[0],lq[1],lq[2],lq[3]);
                }
            }
            __syncthreads();
            // mma: 3 passes, N=32
            #pragma unroll
            for (int ks = 0; ks < 4; ks++) {
                uint32_t aAH = sbu + FS_AH + swz(rowA, ks*2 + kbA);
                uint32_t aH0,aH1,aH2,aH3, aL0,aL1,aL2,aL3;
                ldm_x4(aH0,aH1,aH2,aH3, aAH);
                ldm_x4(aL0,aL1,aL2,aL3, aAH + (FS_AL - FS_AH));
                uint32_t aB0 = sbu + FS_BH + swz(rowB0, ks*2 + kbB);
                uint32_t aB1 = sbu + FS_BH + swz(16 + rowB0, ks*2 + kbB);
                uint32_t bh0,bh1,bh2,bh3, bl0,bl1,bl2,bl3;
                ldm_x4(bh0,bh1,bh2,bh3, aB0);
                ldm_x4(bl0,bl1,bl2,bl3, aB0 + (FS_BL - FS_BH));
                mma_bf16(acc[0], aH0,aH1,aH2,aH3, bh0,bh1);
                mma_bf16(acc[0], aH0,aH1,aH2,aH3, bl0,bl1);
                mma_bf16(acc[0], aL0,aL1,aL2,aL3, bh0,bh1);
                mma_bf16(acc[1], aH0,aH1,aH2,aH3, bh2,bh3);
                mma_bf16(acc[1], aH0,aH1,aH2,aH3, bl2,bl3);
                mma_bf16(acc[1], aL0,aL1,aL2,aL3, bh2,bh3);
                ldm_x4(bh0,bh1,bh2,bh3, aB1);
                ldm_x4(bl0,bl1,bl2,bl3, aB1 + (FS_BL - FS_BH));
                mma_bf16(acc[2], aH0,aH1,aH2,aH3, bh0,bh1);
                mma_bf16(acc[2], aH0,aH1,aH2,aH3, bl0,bl1);
                mma_bf16(acc[2], aL0,aL1,aL2,aL3, bh0,bh1);
                mma_bf16(acc[3], aH0,aH1,aH2,aH3, bh2,bh3);
                mma_bf16(acc[3], aH0,aH1,aH2,aH3, bl2,bl3);
                mma_bf16(acc[3], aL0,aL1,aL2,aL3, bh2,bh3);
            }
        }

        __syncthreads();   // A/B tiles dead; om buffer (overlapping AH) safe to write
        // epilogue: +bias -> smem om buffer [128 px][29 stride]
        #pragma unroll
        for (int nt = 0; nt < 4; nt++) {
            #pragma unroll
            for (int e = 0; e < 4; e++) {
                int o = nt*8 + 2*tq + (e & 1);
                if (o < OMC) {
                    int p = wid*16 + g + (e >> 1)*8;   // local px
                    sOm[p*OMST + o] = acc[nt][e] + sbias[o];
                }
            }
        }
    }
    __syncthreads();   // om ready

    // ================= Phase 2: gather tables from smem om =================
    for (int idx = tid; idx < KKv*MT; idx += TPB) {
        int k = idx >> 7, plt = idx & 127;
        int pxg2 = P0 + plt;
        int y = pxg2 / Wv, x = pxg2 - y*Wv;
        float dy = sOm[plt*OMST + 2*k];
        float dx = sOm[plt*OMST + 2*k+1];
        float mr = sOm[plt*OMST + 18+k];
        float m  = 1.f / (1.f + expf(-mr));
        float pyf = (float)y - 1.f + (float)(k/3) + dy;
        float pxf = (float)x - 1.f + (float)(k%3) + dx;
        float yf = floorf(pyf), xf = floorf(pxf);
        float ly = pyf - yf, lx = pxf - xf;
        int iy0 = (int)yf, ix0 = (int)xf;
        float vy0 = ((unsigned)iy0     < (unsigned)Hv) ? 1.f : 0.f;
        float vy1 = ((unsigned)(iy0+1) < (unsigned)Hv) ? 1.f : 0.f;
        float vx0 = ((unsigned)ix0     < (unsigned)Wv) ? 1.f : 0.f;
        float vx1 = ((unsigned)(ix0+1) < (unsigned)Wv) ? 1.f : 0.f;
        sWgt[idx] = make_float4((1.f-ly)*(1.f-lx)*m*vy0*vx0,
                                (1.f-ly)*lx      *m*vy0*vx1,
                                ly      *(1.f-lx)*m*vy1*vx0,
                                ly      *lx      *m*vy1*vx1);
        int iy0c = min(max(iy0,0),Hv-1), ix0c = min(max(ix0,0),Wv-1);
        int dy1 = (iy0 >= 0 && iy0 <= Hv-2) ? 1 : 0;
        int dx1 = (ix0 >= 0 && ix0 <= Wv-2) ? 1 : 0;
        sBase[idx] = iy0c | (ix0c<<8) | (dy1<<16) | (dx1<<17);
    }
    __syncthreads();   // tables ready; om region may now be overwritten

    // ================= Phase 3: DCN (M=128, N=64) =================
    const float* srcB = src + (size_t)b*Cv*HWv + (size_t)jh*32*HWv;

    float acc[8][4];
    #pragma unroll
    for (int nt = 0; nt < 8; nt++)
        #pragma unroll
        for (int e = 0; e < 4; e++) acc[nt][e] = 0.f;

    for (int cc = 0; cc < NCH; cc++) {
        if (cc) __syncthreads();

        // stage B chunk hi/lo: 64 rows x 8 quads (uint4)
        #pragma unroll
        for (int it = 0; it < 2; it++) {
            int idx = it*TPB + tid;
            int o = idx >> 3, cq = idx & 7;
            int gofs = o*CKK + cc*CKC + cq*8;
            uint32_t d = swz(o, cq);
            *(uint4*)(smem + FS_BH + d) = *(const uint4*)(wh + gofs);
            *(uint4*)(smem + FS_BL + d) = *(const uint4*)(wl + gofs);
        }

        // sample A chunk: fixed tap cc
        {
            int gi = cc*MT + pl;
            float4 cw = sWgt[gi];
            int ev = sBase[gi];
            int iy0 = ev & 255, ix0 = (ev>>8) & 255;
            int iy1 = iy0 + ((ev>>16)&1), ix1 = ix0 + ((ev>>17)&1);
            const float* pA = srcB + iy0*Wv + ix0;
            const float* pB = srcB + iy0*Wv + ix1;
            const float* pC = srcB + iy1*Wv + ix0;
            const float* pD = srcB + iy1*Wv + ix1;
            #pragma unroll
            for (int q = 0; q < 4; q++) {
                float vA[8], vB[8], vC[8], vD[8];
                #pragma unroll
                for (int ci = 0; ci < 8; ci++) {
                    size_t co = (size_t)(8*q + ci)*HWv;
                    vA[ci] = __ldg(pA + co);
                    vB[ci] = __ldg(pB + co);
                    vC[ci] = __ldg(pC + co);
                    vD[ci] = __ldg(pD + co);
                }
                uint32_t hq[4], lq[4];
                #pragma unroll
                for (int wi = 0; wi < 4; wi++) {
                    float s0 = cw.x*vA[2*wi]   + cw.y*vB[2*wi]
                             + cw.z*vC[2*wi]   + cw.w*vD[2*wi];
                    float s1 = cw.x*vA[2*wi+1] + cw.y*vB[2*wi+1]
                             + cw.z*vC[2*wi+1] + cw.w*vD[2*wi+1];
                    uint32_t p0 = split_pack(s0), p1 = split_pack(s1);
                    hq[wi] = __byte_perm(p0, p1, 0x5410);
                    lq[wi] = __byte_perm(p0, p1, 0x7632);
                }
                uint32_t d = swz(pl, jh*4 + q);
                *(uint4*)(smem + FS_AH + d) = make_uint4(hq[0],hq[1],hq[2],hq[3]);
                *(uint4*)(smem + FS_AL + d) = make_uint4(lq[0],lq[1],lq[2],lq[3]);
            }
        }
        __syncthreads();

        // MMA: 4 k-steps x 8 n-tiles x 3 passes
        #pragma unroll
        for (int ks = 0; ks < 4; ks++) {
            uint32_t aAH = sbu + FS_AH + swz(rowA, ks*2 + kbA);
            uint32_t aH0,aH1,aH2,aH3, aL0,aL1,aL2,aL3;
            ldm_x4(aH0,aH1,aH2,aH3, aAH);
            ldm_x4(aL0,aL1,aL2,aL3, aAH + (FS_AL - FS_AH));
            #pragma unroll
            for (int np = 0; np < 4; np++) {
                uint32_t aB = sbu + FS_BH + swz(np*16 + rowB0, ks*2 + kbB);
                uint32_t bh0,bh1,bh2,bh3, bl0,bl1,bl2,bl3;
                ldm_x4(bh0,bh1,bh2,bh3, aB);
                ldm_x4(bl0,bl1,bl2,bl3, aB + (FS_BL - FS_BH));
                mma_bf16(acc[2*np],   aH0,aH1,aH2,aH3, bh0,bh1);
                mma_bf16(acc[2*np],   aH0,aH1,aH2,aH3, bl0,bl1);
                mma_bf16(acc[2*np],   aL0,aL1,aL2,aL3, bh0,bh1);
                mma_bf16(acc[2*np+1], aH0,aH1,aH2,aH3, bh2,bh3);
                mma_bf16(acc[2*np+1], aH0,aH1,aH2,aH3, bl2,bl3);
                mma_bf16(acc[2*np+1], aL0,aL1,aL2,aL3, bh2,bh3);
            }
        }
    }

    // epilogue: BN (+residual) + exact GELU (+ hi/lo split for pass 1)
    const int px0 = P0 + wid*16 + g;
    const size_t bofs = (size_t)b*Cv*HWv;
    #pragma unroll
    for (int nt = 0; nt < 8; nt++) {
        #pragma unroll
        for (int e = 0; e < 4; e++) {
            int o  = nt*8 + 2*tq + (e & 1);
            int pxo = px0 + (e >> 1)*8;
            float v = acc[nt][e] * sSc[o] + sSh[o];
            size_t ofs = bofs + (size_t)o*HWv + pxo;
            if (identity) v += __ldg(identity + ofs);
            v = gelu_exact(v);
            out[ofs] = v;
            if (midhl) midhl[ofs] = split_pack(v);
        }
    }
}

// ---------------------------------------------------------------------------
extern "C" void kernel_launch(void* const* d_in, const int* in_sizes, int n_in,
                              void* d_out, int out_size)
{
    const float* x      = (const float*)d_in[0];
    const float* w_om1  = (const float*)d_in[1];
    const float* b_om1  = (const float*)d_in[2];
    const float* w_dcn1 = (const float*)d_in[3];
    const float* bn1g   = (const float*)d_in[4];
    const float* bn1b   = (const float*)d_in[5];
    const float* bn1m   = (const float*)d_in[6];
    const float* bn1v   = (const float*)d_in[7];
    const float* w_om2  = (const float*)d_in[8];
    const float* b_om2  = (const float*)d_in[9];
    const float* w_dcn2 = (const float*)d_in[10];
    const float* bn2g   = (const float*)d_in[11];
    const float* bn2b   = (const float*)d_in[12];
    const float* bn2m   = (const float*)d_in[13];
    const float* bn2v   = (const float*)d_in[14];
    float* out = (float*)d_out;

    float *mid;
    uint32_t *xhl, *midhl;
    __nv_bfloat16 *wh1, *wl1, *wh2, *wl2, *omh1, *oml1, *omh2, *oml2;
    cudaGetSymbolAddress((void**)&mid,   g_mid);
    cudaGetSymbolAddress((void**)&xhl,   g_xhl);
    cudaGetSymbolAddress((void**)&midhl, g_midhl);
    cudaGetSymbolAddress((void**)&wh1,   g_wh1);
    cudaGetSymbolAddress((void**)&wl1,   g_wl1);
    cudaGetSymbolAddress((void**)&wh2,   g_wh2);
    cudaGetSymbolAddress((void**)&wl2,   g_wl2);
    cudaGetSymbolAddress((void**)&omh1,  g_omh1);
    cudaGetSymbolAddress((void**)&oml1,  g_oml1);
    cudaGetSymbolAddress((void**)&omh2,  g_omh2);
    cudaGetSymbolAddress((void**)&oml2,  g_oml2);

    cudaFuncSetAttribute(fused_kernel, cudaFuncAttributeMaxDynamicSharedMemorySize, FS_TOT);

    prep_kernel<<<(Bv*Cv*HWv + 255)/256, 256>>>(x, w_dcn1, w_dcn2, w_om1, w_om2);

    dim3 grid(HWv/MT, Bv);   // 200 x 4

    fused_kernel<<<grid, TPB, FS_TOT>>>(xhl, omh1, oml1, b_om1,
        x, wh1, wl1, bn1g, bn1b, bn1m, bn1v, nullptr, mid, midhl);

    fused_kernel<<<grid, TPB, FS_TOT>>>(midhl, omh2, oml2, b_om2,
        mid, wh2, wl2, bn2g, bn2b, bn2m, bn2v, x, out, nullptr);
}

// round 13
// speedup vs baseline: 1.4716x; 1.0447x over previous
#include <cuda_runtime.h>
#include <cuda_bf16.h>
#include <math.h>
#include <stdint.h>

#define Bv   4
#define Cv   64
#define Hv   160
#define Wv   160
#define HWv  25600
#define KKv  9
#define OMC  27
#define CKK  576

#define MT    128          // px per block tile (M)
#define TPB   256
#define CKC   64           // K chunk = one kernel tap (64 channels)
#define NCH   9

// swizzled tile: row = 128B = 8 uint4; quad col stored at (cq ^ (row&7))

// fused smem map (bytes)
#define FS_SC    0          // float[64]
#define FS_SH    256        // float[64]
#define FS_BIAS  512        // float[32]
#define FS_WGT   1024       // float4[1152] = 18432 -> [1024, 19456)
#define FS_BASE  19456      // int[1152]    =  4608 -> [19456, 24064)
#define FS_AH    24576      // 16384
#define FS_AL    40960      // 16384
#define FS_BH    57344      // 8192
#define FS_BL    65536      // 8192
#define FS_OM    24576      // float[128*29] = 14848 (overlaps AH region)
#define OMST     29         // om row stride (words), conflict-free
#define FS_TOT   73728

// scratch
__device__ float    g_mid[Bv*Cv*HWv];
__device__ uint32_t g_xhl[Bv*Cv*HWv];     // packed (bf16 hi | bf16 lo<<16)
__device__ uint32_t g_midhl[Bv*Cv*HWv];
// k-major weights: [o][k*64 + c]
__device__ __align__(16) __nv_bfloat16 g_wh1[Cv*CKK], g_wl1[Cv*CKK];
__device__ __align__(16) __nv_bfloat16 g_wh2[Cv*CKK], g_wl2[Cv*CKK];
__device__ __align__(16) __nv_bfloat16 g_omh1[32*CKK], g_oml1[32*CKK];
__device__ __align__(16) __nv_bfloat16 g_omh2[32*CKK], g_oml2[32*CKK];

__device__ __forceinline__ float gelu_exact(float v) {
    return 0.5f * v * (1.0f + erff(v * 0.70710678118654752f));
}
__device__ __forceinline__ uint32_t split_pack(float v) {
    __nv_bfloat16 h = __float2bfloat16(v);
    __nv_bfloat16 l = __float2bfloat16(v - __bfloat162float(h));
    return (uint32_t)__bfloat16_as_ushort(h) | ((uint32_t)__bfloat16_as_ushort(l) << 16);
}
__device__ __forceinline__ uint32_t smem_u32(const void* p) {
    uint32_t a;
    asm("{ .reg .u64 t; cvta.to.shared.u64 t, %1; cvt.u32.u64 %0, t; }" : "=r"(a) : "l"(p));
    return a;
}
__device__ __forceinline__ void mma_bf16(float* d,
    uint32_t a0, uint32_t a1, uint32_t a2, uint32_t a3, uint32_t b0, uint32_t b1)
{
    asm volatile(
        "mma.sync.aligned.m16n8k16.row.col.f32.bf16.bf16.f32 "
        "{%0,%1,%2,%3},{%4,%5,%6,%7},{%8,%9},{%0,%1,%2,%3};"
        : "+f"(d[0]), "+f"(d[1]), "+f"(d[2]), "+f"(d[3])
        : "r"(a0), "r"(a1), "r"(a2), "r"(a3), "r"(b0), "r"(b1));
}
__device__ __forceinline__ void ldm_x4(uint32_t& r0, uint32_t& r1, uint32_t& r2, uint32_t& r3, uint32_t addr) {
    asm volatile("ldmatrix.sync.aligned.m8n8.x4.shared.b16 {%0,%1,%2,%3}, [%4];"
                 : "=r"(r0), "=r"(r1), "=r"(r2), "=r"(r3) : "r"(addr));
}
__device__ __forceinline__ uint32_t swz(int row, int cq) {
    return (uint32_t)(row*128 + ((cq ^ (row & 7)) << 4));
}

// ---------------------------------------------------------------------------
// prep: x split vectorized float4; weights permuted to k-major [o][k*64+c]
// ---------------------------------------------------------------------------
__global__ void prep_kernel(const float* __restrict__ x,
                            const float* __restrict__ wd1, const float* __restrict__ wd2,
                            const float* __restrict__ wom1, const float* __restrict__ wom2)
{
    int i = blockIdx.x * 256 + threadIdx.x;
    if (i < (Bv*Cv*HWv)/4) {
        float4 v = __ldg((const float4*)x + i);
        uint4 r;
        r.x = split_pack(v.x); r.y = split_pack(v.y);
        r.z = split_pack(v.z); r.w = split_pack(v.w);
        *((uint4*)g_xhl + i) = r;
    }
    if (i < Cv*CKK) {
        int o = i / CKK, r = i - o*CKK;
        int c = r / 9, k = r - 9*c;
        int dst = o*CKK + k*64 + c;
        float v1 = wd1[i];
        __nv_bfloat16 h1 = __float2bfloat16(v1);
        g_wh1[dst] = h1;
        g_wl1[dst] = __float2bfloat16(v1 - __bfloat162float(h1));
        float v2 = wd2[i];
        __nv_bfloat16 h2 = __float2bfloat16(v2);
        g_wh2[dst] = h2;
        g_wl2[dst] = __float2bfloat16(v2 - __bfloat162float(h2));
    }
    if (i < 32*CKK) {
        int o = i / CKK, r = i - o*CKK;
        int c = r / 9, k = r - 9*c;
        int dst = o*CKK + k*64 + c;
        float v1 = (i < OMC*CKK) ? wom1[i] : 0.f;
        __nv_bfloat16 h1 = __float2bfloat16(v1);
        g_omh1[dst] = h1;
        g_oml1[dst] = __float2bfloat16(v1 - __bfloat162float(h1));
        float v2 = (i < OMC*CKK) ? wom2[i] : 0.f;
        __nv_bfloat16 h2 = __float2bfloat16(v2);
        g_omh2[dst] = h2;
        g_oml2[dst] = __float2bfloat16(v2 - __bfloat162float(h2));
    }
}

// ---------------------------------------------------------------------------
// Fused BasicBlock half: offc (mma) -> om in smem -> tables -> dcn (mma)
// dcn phase uses 32px x 32o warp tiles (B-fragment dedup).
// ---------------------------------------------------------------------------
__global__ __launch_bounds__(TPB, 3) void fused_kernel(
    const uint32_t* __restrict__ xhl_in,      // offc input, packed hi/lo
    const __nv_bfloat16* __restrict__ omwh,   // offc weights hi  [32][576] k-major
    const __nv_bfloat16* __restrict__ omwl,   // offc weights lo
    const float* __restrict__ ombias,
    const float* __restrict__ src,            // dcn gather source (fp32)
    const __nv_bfloat16* __restrict__ wh,     // dcn weights hi [64][576] k-major
    const __nv_bfloat16* __restrict__ wl,
    const float* __restrict__ bng,
    const float* __restrict__ bnb,
    const float* __restrict__ bnm,
    const float* __restrict__ bnv,
    const float* __restrict__ identity,
    float* __restrict__ out,
    uint32_t* __restrict__ midhl)
{
    extern __shared__ char smem[];
    const uint32_t sbu = smem_u32(smem);
    float*  sSc   = (float*)(smem + FS_SC);
    float*  sSh   = (float*)(smem + FS_SH);
    float*  sbias = (float*)(smem + FS_BIAS);
    float4* sWgt  = (float4*)(smem + FS_WGT);
    int*    sBase = (int*)(smem + FS_BASE);
    float*  sOm   = (float*)(smem + FS_OM);

    const int tid  = threadIdx.x, wid = tid >> 5, lane = tid & 31;
    const int g    = lane >> 2, tq = lane & 3;
    const int b    = blockIdx.y;
    const int P0   = blockIdx.x * MT;

    if (tid < 64) {
        float sc = bng[tid] * rsqrtf(bnv[tid] + 1e-5f);
        sSc[tid] = sc;
        sSh[tid] = bnb[tid] - bnm[tid]*sc;
    } else if (tid < 96) {
        int o = tid - 64;
        sbias[o] = (o < OMC) ? ombias[o] : 0.f;
    }

    const int pl = tid & 127, jh = tid >> 7;
    const int pg = P0 + pl;
    const int py = pg / Wv, px = pg - py*Wv;

    // ldmatrix lane geometry
    const int laneA = lane & 15;
    const int rowA = wid*16 + laneA;                  // offc-phase A rows
    const int kbA  = (lane & 16) ? 1 : 0;
    const int rowB0 = (lane & 7) + ((lane & 16) ? 8 : 0);
    const int kbB   = (lane & 8) ? 1 : 0;

    // ================= Phase 1: offset/mask conv (M=128, N=32) =================
    {
        const uint32_t* srcO = xhl_in + (size_t)b*Cv*HWv + (size_t)(jh*32)*HWv;
        float acc[4][4];
        #pragma unroll
        for (int nt = 0; nt < 4; nt++)
            #pragma unroll
            for (int e = 0; e < 4; e++) acc[nt][e] = 0.f;

        for (int cc = 0; cc < NCH; cc++) {
            if (cc) __syncthreads();
            // stage B: 32 rows x 8 quads hi/lo
            {
                int o = tid >> 3, cq = tid & 7;
                int gofs = o*CKK + cc*CKC + cq*8;
                uint32_t d = swz(o, cq);
                *(uint4*)(smem + FS_BH + d) = *(const uint4*)(omwh + gofs);
                *(uint4*)(smem + FS_BL + d) = *(const uint4*)(omwl + gofs);
            }
            // build A: fixed tap cc
            {
                int yy = py + cc/3 - 1, xx = px + (cc % 3) - 1;
                bool val = ((unsigned)yy < (unsigned)Hv) && ((unsigned)xx < (unsigned)Wv);
                const uint32_t* p = srcO + yy*Wv + xx;
                #pragma unroll
                for (int q = 0; q < 4; q++) {
                    uint32_t hq[4], lq[4];
                    #pragma unroll
                    for (int wi = 0; wi < 4; wi++) {
                        int c0 = 8*q + 2*wi;
                        uint32_t v0 = val ? __ldg(p + (size_t)c0*HWv) : 0u;
                        uint32_t v1 = val ? __ldg(p + (size_t)(c0+1)*HWv) : 0u;
                        hq[wi] = __byte_perm(v0, v1, 0x5410);
                        lq[wi] = __byte_perm(v0, v1, 0x7632);
                    }
                    uint32_t d = swz(pl, jh*4 + q);
                    *(uint4*)(smem + FS_AH + d) = make_uint4(hq[0],hq[1],hq[2],hq[3]);
                    *(uint4*)(smem + FS_AL + d) = make_uint4(lq[0],lq[1],lq[2],lq[3]);
                }
            }
            __syncthreads();
            // mma: 3 passes, N=32
            #pragma unroll
            for (int ks = 0; ks < 4; ks++) {
                uint32_t aAH = sbu + FS_AH + swz(rowA, ks*2 + kbA);
                uint32_t aH0,aH1,aH2,aH3, aL0,aL1,aL2,aL3;
                ldm_x4(aH0,aH1,aH2,aH3, aAH);
                ldm_x4(aL0,aL1,aL2,aL3, aAH + (FS_AL - FS_AH));
                uint32_t aB0 = sbu + FS_BH + swz(rowB0, ks*2 + kbB);
                uint32_t aB1 = sbu + FS_BH + swz(16 + rowB0, ks*2 + kbB);
                uint32_t bh0,bh1,bh2,bh3, bl0,bl1,bl2,bl3;
                ldm_x4(bh0,bh1,bh2,bh3, aB0);
                ldm_x4(bl0,bl1,bl2,bl3, aB0 + (FS_BL - FS_BH));
                mma_bf16(acc[0], aH0,aH1,aH2,aH3, bh0,bh1);
                mma_bf16(acc[0], aH0,aH1,aH2,aH3, bl0,bl1);
                mma_bf16(acc[0], aL0,aL1,aL2,aL3, bh0,bh1);
                mma_bf16(acc[1], aH0,aH1,aH2,aH3, bh2,bh3);
                mma_bf16(acc[1], aH0,aH1,aH2,aH3, bl2,bl3);
                mma_bf16(acc[1], aL0,aL1,aL2,aL3, bh2,bh3);
                ldm_x4(bh0,bh1,bh2,bh3, aB1);
                ldm_x4(bl0,bl1,bl2,bl3, aB1 + (FS_BL - FS_BH));
                mma_bf16(acc[2], aH0,aH1,aH2,aH3, bh0,bh1);
                mma_bf16(acc[2], aH0,aH1,aH2,aH3, bl0,bl1);
                mma_bf16(acc[2], aL0,aL1,aL2,aL3, bh0,bh1);
                mma_bf16(acc[3], aH0,aH1,aH2,aH3, bh2,bh3);
                mma_bf16(acc[3], aH0,aH1,aH2,aH3, bl2,bl3);
                mma_bf16(acc[3], aL0,aL1,aL2,aL3, bh2,bh3);
            }
        }

        __syncthreads();   // A/B tiles dead; om buffer safe to write
        #pragma unroll
        for (int nt = 0; nt < 4; nt++) {
            #pragma unroll
            for (int e = 0; e < 4; e++) {
                int o = nt*8 + 2*tq + (e & 1);
                if (o < OMC) {
                    int p = wid*16 + g + (e >> 1)*8;   // local px
                    sOm[p*OMST + o] = acc[nt][e] + sbias[o];
                }
            }
        }
    }
    __syncthreads();   // om ready

    // ================= Phase 2: gather tables from smem om =================
    for (int idx = tid; idx < KKv*MT; idx += TPB) {
        int k = idx >> 7, plt = idx & 127;
        int pxg2 = P0 + plt;
        int y = pxg2 / Wv, x = pxg2 - y*Wv;
        float dy = sOm[plt*OMST + 2*k];
        float dx = sOm[plt*OMST + 2*k+1];
        float mr = sOm[plt*OMST + 18+k];
        float m  = 1.f / (1.f + expf(-mr));
        float pyf = (float)y - 1.f + (float)(k/3) + dy;
        float pxf = (float)x - 1.f + (float)(k%3) + dx;
        float yf = floorf(pyf), xf = floorf(pxf);
        float ly = pyf - yf, lx = pxf - xf;
        int iy0 = (int)yf, ix0 = (int)xf;
        float vy0 = ((unsigned)iy0     < (unsigned)Hv) ? 1.f : 0.f;
        float vy1 = ((unsigned)(iy0+1) < (unsigned)Hv) ? 1.f : 0.f;
        float vx0 = ((unsigned)ix0     < (unsigned)Wv) ? 1.f : 0.f;
        float vx1 = ((unsigned)(ix0+1) < (unsigned)Wv) ? 1.f : 0.f;
        sWgt[idx] = make_float4((1.f-ly)*(1.f-lx)*m*vy0*vx0,
                                (1.f-ly)*lx      *m*vy0*vx1,
                                ly      *(1.f-lx)*m*vy1*vx0,
                                ly      *lx      *m*vy1*vx1);
        int iy0c = min(max(iy0,0),Hv-1), ix0c = min(max(ix0,0),Wv-1);
        int dy1 = (iy0 >= 0 && iy0 <= Hv-2) ? 1 : 0;
        int dx1 = (ix0 >= 0 && ix0 <= Wv-2) ? 1 : 0;
        sBase[idx] = iy0c | (ix0c<<8) | (dy1<<16) | (dx1<<17);
    }
    __syncthreads();

    // ================= Phase 3: DCN (M=128, N=64), warp tile 32px x 32o ======
    const float* srcB = src + (size_t)b*Cv*HWv + (size_t)jh*32*HWv;
    const int wq = wid & 3, wn = wid >> 2;   // px quarter, o half

    float acc[2][4][4];
    #pragma unroll
    for (int mt = 0; mt < 2; mt++)
        #pragma unroll
        for (int nt = 0; nt < 4; nt++)
            #pragma unroll
            for (int e = 0; e < 4; e++) acc[mt][nt][e] = 0.f;

    for (int cc = 0; cc < NCH; cc++) {
        if (cc) __syncthreads();

        // stage B chunk hi/lo: 64 rows x 8 quads (uint4)
        #pragma unroll
        for (int it = 0; it < 2; it++) {
            int idx = it*TPB + tid;
            int o = idx >> 3, cq = idx & 7;
            int gofs = o*CKK + cc*CKC + cq*8;
            uint32_t d = swz(o, cq);
            *(uint4*)(smem + FS_BH + d) = *(const uint4*)(wh + gofs);
            *(uint4*)(smem + FS_BL + d) = *(const uint4*)(wl + gofs);
        }

        // sample A chunk: fixed tap cc
        {
            int gi = cc*MT + pl;
            float4 cw = sWgt[gi];
            int ev = sBase[gi];
            int iy0 = ev & 255, ix0 = (ev>>8) & 255;
            int iy1 = iy0 + ((ev>>16)&1), ix1 = ix0 + ((ev>>17)&1);
            const float* pA = srcB + iy0*Wv + ix0;
            const float* pB = srcB + iy0*Wv + ix1;
            const float* pC = srcB + iy1*Wv + ix0;
            const float* pD = srcB + iy1*Wv + ix1;
            #pragma unroll
            for (int q = 0; q < 4; q++) {
                float vA[8], vB[8], vC[8], vD[8];
                #pragma unroll
                for (int ci = 0; ci < 8; ci++) {
                    size_t co = (size_t)(8*q + ci)*HWv;
                    vA[ci] = __ldg(pA + co);
                    vB[ci] = __ldg(pB + co);
                    vC[ci] = __ldg(pC + co);
                    vD[ci] = __ldg(pD + co);
                }
                uint32_t hq[4], lq[4];
                #pragma unroll
                for (int wi = 0; wi < 4; wi++) {
                    float s0 = cw.x*vA[2*wi]   + cw.y*vB[2*wi]
                             + cw.z*vC[2*wi]   + cw.w*vD[2*wi];
                    float s1 = cw.x*vA[2*wi+1] + cw.y*vB[2*wi+1]
                             + cw.z*vC[2*wi+1] + cw.w*vD[2*wi+1];
                    uint32_t p0 = split_pack(s0), p1 = split_pack(s1);
                    hq[wi] = __byte_perm(p0, p1, 0x5410);
                    lq[wi] = __byte_perm(p0, p1, 0x7632);
                }
                uint32_t d = swz(pl, jh*4 + q);
                *(uint4*)(smem + FS_AH + d) = make_uint4(hq[0],hq[1],hq[2],hq[3]);
                *(uint4*)(smem + FS_AL + d) = make_uint4(lq[0],lq[1],lq[2],lq[3]);
            }
        }
        __syncthreads();

        // MMA: 4 k-steps; warp covers 32 px (2 m-tiles) x 32 o (2 n-pairs)
        #pragma unroll
        for (int ks = 0; ks < 4; ks++) {
            uint32_t aH[2][4], aL[2][4];
            #pragma unroll
            for (int mt = 0; mt < 2; mt++) {
                uint32_t aAH = sbu + FS_AH + swz(wq*32 + mt*16 + laneA, ks*2 + kbA);
                ldm_x4(aH[mt][0],aH[mt][1],aH[mt][2],aH[mt][3], aAH);
                ldm_x4(aL[mt][0],aL[mt][1],aL[mt][2],aL[mt][3], aAH + (FS_AL - FS_AH));
            }
            #pragma unroll
            for (int np = 0; np < 2; np++) {
                uint32_t aB = sbu + FS_BH + swz(wn*32 + np*16 + rowB0, ks*2 + kbB);
                uint32_t bh0,bh1,bh2,bh3, bl0,bl1,bl2,bl3;
                ldm_x4(bh0,bh1,bh2,bh3, aB);
                ldm_x4(bl0,bl1,bl2,bl3, aB + (FS_BL - FS_BH));
                #pragma unroll
                for (int mt = 0; mt < 2; mt++) {
                    mma_bf16(acc[mt][2*np],   aH[mt][0],aH[mt][1],aH[mt][2],aH[mt][3], bh0,bh1);
                    mma_bf16(acc[mt][2*np],   aH[mt][0],aH[mt][1],aH[mt][2],aH[mt][3], bl0,bl1);
                    mma_bf16(acc[mt][2*np],   aL[mt][0],aL[mt][1],aL[mt][2],aL[mt][3], bh0,bh1);
                    mma_bf16(acc[mt][2*np+1], aH[mt][0],aH[mt][1],aH[mt][2],aH[mt][3], bh2,bh3);
                    mma_bf16(acc[mt][2*np+1], aH[mt][0],aH[mt][1],aH[mt][2],aH[mt][3], bl2,bl3);
                    mma_bf16(acc[mt][2*np+1], aL[mt][0],aL[mt][1],aL[mt][2],aL[mt][3], bh2,bh3);
                }
            }
        }
    }

    // epilogue: BN (+residual) + exact GELU (+ hi/lo split for pass 1)
    const size_t bofs = (size_t)b*Cv*HWv;
    #pragma unroll
    for (int mt = 0; mt < 2; mt++) {
        const int px0 = P0 + wq*32 + mt*16 + g;
        #pragma unroll
        for (int nt = 0; nt < 4; nt++) {
            #pragma unroll
            for (int e = 0; e < 4; e++) {
                int o  = wn*32 + nt*8 + 2*tq + (e & 1);
                int pxo = px0 + (e >> 1)*8;
                float v = acc[mt][nt][e] * sSc[o] + sSh[o];
                size_t ofs = bofs + (size_t)o*HWv + pxo;
                if (identity) v += __ldg(identity + ofs);
                v = gelu_exact(v);
                out[ofs] = v;
                if (midhl) midhl[ofs] = split_pack(v);
            }
        }
    }
}

// ---------------------------------------------------------------------------
extern "C" void kernel_launch(void* const* d_in, const int* in_sizes, int n_in,
                              void* d_out, int out_size)
{
    const float* x      = (const float*)d_in[0];
    const float* w_om1  = (const float*)d_in[1];
    const float* b_om1  = (const float*)d_in[2];
    const float* w_dcn1 = (const float*)d_in[3];
    const float* bn1g   = (const float*)d_in[4];
    const float* bn1b   = (const float*)d_in[5];
    const float* bn1m   = (const float*)d_in[6];
    const float* bn1v   = (const float*)d_in[7];
    const float* w_om2  = (const float*)d_in[8];
    const float* b_om2  = (const float*)d_in[9];
    const float* w_dcn2 = (const float*)d_in[10];
    const float* bn2g   = (const float*)d_in[11];
    const float* bn2b   = (const float*)d_in[12];
    const float* bn2m   = (const float*)d_in[13];
    const float* bn2v   = (const float*)d_in[14];
    float* out = (float*)d_out;

    float *mid;
    uint32_t *xhl, *midhl;
    __nv_bfloat16 *wh1, *wl1, *wh2, *wl2, *omh1, *oml1, *omh2, *oml2;
    cudaGetSymbolAddress((void**)&mid,   g_mid);
    cudaGetSymbolAddress((void**)&xhl,   g_xhl);
    cudaGetSymbolAddress((void**)&midhl, g_midhl);
    cudaGetSymbolAddress((void**)&wh1,   g_wh1);
    cudaGetSymbolAddress((void**)&wl1,   g_wl1);
    cudaGetSymbolAddress((void**)&wh2,   g_wh2);
    cudaGetSymbolAddress((void**)&wl2,   g_wl2);
    cudaGetSymbolAddress((void**)&omh1,  g_omh1);
    cudaGetSymbolAddress((void**)&oml1,  g_oml1);
    cudaGetSymbolAddress((void**)&omh2,  g_omh2);
    cudaGetSymbolAddress((void**)&oml2,  g_oml2);

    cudaFuncSetAttribute(fused_kernel, cudaFuncAttributeMaxDynamicSharedMemorySize, FS_TOT);

    prep_kernel<<<((Bv*Cv*HWv)/4 + 255)/256, 256>>>(x, w_dcn1, w_dcn2, w_om1, w_om2);

    dim3 grid(HWv/MT, Bv);   // 200 x 4

    fused_kernel<<<grid, TPB, FS_TOT>>>(xhl, omh1, oml1, b_om1,
        x, wh1, wl1, bn1g, bn1b, bn1m, bn1v, nullptr, mid, midhl);

    fused_kernel<<<grid, TPB, FS_TOT>>>(midhl, omh2, oml2, b_om2,
        mid, wh2, wl2, bn2g, bn2b, bn2m, bn2v, x, out, nullptr);
}

// round 14
// speedup vs baseline: 1.6295x; 1.1073x over previous
#include <cuda_runtime.h>
#include <cuda_bf16.h>
#include <math.h>
#include <stdint.h>

#define Bv   4
#define Cv   64
#define Hv   160
#define Wv   160
#define HWv  25600
#define KKv  9
#define OMC  27
#define CKK  576

#define MT    128          // px per block tile (M)
#define TPB   256
#define CKC   64           // K chunk = one kernel tap (64 channels)
#define NCH   9

// swizzled tile: row = 128B = 8 uint4; quad col stored at (cq ^ (row&7))

// fused smem map (bytes)
#define FS_SC    0          // float[64]
#define FS_SH    256        // float[64]
#define FS_BIAS  512        // float[32]
#define FS_WGT   1024       // float4[1152] = 18432 -> [1024, 19456)
#define FS_BASE  19456      // int[1152]    =  4608 -> [19456, 24064)
#define FS_AH    24576      // 16384
#define FS_AL    40960      // 16384
#define FS_BH    57344      // 8192
#define FS_BL    65536      // 8192
#define FS_OM    24576      // float[128*29] = 14848 (overlaps AH region)
#define OMST     29         // om row stride (words), conflict-free
#define FS_TOT   73728

// scratch
__device__ float          g_mid[Bv*Cv*HWv];     // layer-1 output fp32 (dcn-2 gather src)
__device__ __nv_bfloat16  g_midh[Bv*Cv*HWv];    // layer-1 output bf16 (offc-2 input)
// k-major weights: [o][k*64 + c]
__device__ __align__(16) __nv_bfloat16 g_wh1[Cv*CKK], g_wl1[Cv*CKK];
__device__ __align__(16) __nv_bfloat16 g_wh2[Cv*CKK], g_wl2[Cv*CKK];
__device__ __align__(16) __nv_bfloat16 g_omh1[32*CKK];
__device__ __align__(16) __nv_bfloat16 g_omh2[32*CKK];

__device__ __forceinline__ float gelu_exact(float v) {
    return 0.5f * v * (1.0f + erff(v * 0.70710678118654752f));
}
__device__ __forceinline__ uint32_t split_pack(float v) {
    __nv_bfloat16 h = __float2bfloat16(v);
    __nv_bfloat16 l = __float2bfloat16(v - __bfloat162float(h));
    return (uint32_t)__bfloat16_as_ushort(h) | ((uint32_t)__bfloat16_as_ushort(l) << 16);
}
__device__ __forceinline__ uint32_t pack_bf16x2(float lo, float hi) {
    uint32_t r;
    asm("cvt.rn.bf16x2.f32 %0, %1, %2;" : "=r"(r) : "f"(hi), "f"(lo));
    return r;
}
__device__ __forceinline__ uint32_t smem_u32(const void* p) {
    uint32_t a;
    asm("{ .reg .u64 t; cvta.to.shared.u64 t, %1; cvt.u32.u64 %0, t; }" : "=r"(a) : "l"(p));
    return a;
}
__device__ __forceinline__ void mma_bf16(float* d,
    uint32_t a0, uint32_t a1, uint32_t a2, uint32_t a3, uint32_t b0, uint32_t b1)
{
    asm volatile(
        "mma.sync.aligned.m16n8k16.row.col.f32.bf16.bf16.f32 "
        "{%0,%1,%2,%3},{%4,%5,%6,%7},{%8,%9},{%0,%1,%2,%3};"
        : "+f"(d[0]), "+f"(d[1]), "+f"(d[2]), "+f"(d[3])
        : "r"(a0), "r"(a1), "r"(a2), "r"(a3), "r"(b0), "r"(b1));
}
__device__ __forceinline__ void ldm_x4(uint32_t& r0, uint32_t& r1, uint32_t& r2, uint32_t& r3, uint32_t addr) {
    asm volatile("ldmatrix.sync.aligned.m8n8.x4.shared.b16 {%0,%1,%2,%3}, [%4];"
                 : "=r"(r0), "=r"(r1), "=r"(r2), "=r"(r3) : "r"(addr));
}
__device__ __forceinline__ uint32_t swz(int row, int cq) {
    return (uint32_t)(row*128 + ((cq ^ (row & 7)) << 4));
}

// ---------------------------------------------------------------------------
// prep: weights only (k-major [o][k*64+c]); dcn hi/lo, offc hi-only
// ---------------------------------------------------------------------------
__global__ void prep_kernel(const float* __restrict__ wd1, const float* __restrict__ wd2,
                            const float* __restrict__ wom1, const float* __restrict__ wom2)
{
    int i = blockIdx.x * 256 + threadIdx.x;
    if (i < Cv*CKK) {
        int o = i / CKK, r = i - o*CKK;
        int c = r / 9, k = r - 9*c;
        int dst = o*CKK + k*64 + c;
        float v1 = wd1[i];
        __nv_bfloat16 h1 = __float2bfloat16(v1);
        g_wh1[dst] = h1;
        g_wl1[dst] = __float2bfloat16(v1 - __bfloat162float(h1));
        float v2 = wd2[i];
        __nv_bfloat16 h2 = __float2bfloat16(v2);
        g_wh2[dst] = h2;
        g_wl2[dst] = __float2bfloat16(v2 - __bfloat162float(h2));
    }
    if (i < 32*CKK) {
        int o = i / CKK, r = i - o*CKK;
        int c = r / 9, k = r - 9*c;
        int dst = o*CKK + k*64 + c;
        g_omh1[dst] = __float2bfloat16((i < OMC*CKK) ? wom1[i] : 0.f);
        g_omh2[dst] = __float2bfloat16((i < OMC*CKK) ? wom2[i] : 0.f);
    }
}

// ---------------------------------------------------------------------------
// Fused BasicBlock half: offc (1-pass bf16 mma) -> om in smem -> tables ->
// dcn (3-pass hi/lo mma, 32px x 32o warp tiles).
// F32IN: offc input dtype (true: fp32 x; false: bf16 midh).
// ---------------------------------------------------------------------------
template<bool F32IN>
__global__ __launch_bounds__(TPB, 3) void fused_kernel(
    const void* __restrict__ omin,            // offc input (fp32 or bf16, NCHW)
    const __nv_bfloat16* __restrict__ omwh,   // offc weights hi [32][576] k-major
    const float* __restrict__ ombias,
    const float* __restrict__ src,            // dcn gather source (fp32)
    const __nv_bfloat16* __restrict__ wh,     // dcn weights hi [64][576] k-major
    const __nv_bfloat16* __restrict__ wl,
    const float* __restrict__ bng,
    const float* __restrict__ bnb,
    const float* __restrict__ bnm,
    const float* __restrict__ bnv,
    const float* __restrict__ identity,
    float* __restrict__ out,
    __nv_bfloat16* __restrict__ midh)
{
    extern __shared__ char smem[];
    const uint32_t sbu = smem_u32(smem);
    float*  sSc   = (float*)(smem + FS_SC);
    float*  sSh   = (float*)(smem + FS_SH);
    float*  sbias = (float*)(smem + FS_BIAS);
    float4* sWgt  = (float4*)(smem + FS_WGT);
    int*    sBase = (int*)(smem + FS_BASE);
    float*  sOm   = (float*)(smem + FS_OM);

    const int tid  = threadIdx.x, wid = tid >> 5, lane = tid & 31;
    const int g    = lane >> 2, tq = lane & 3;
    const int b    = blockIdx.y;
    const int P0   = blockIdx.x * MT;

    if (tid < 64) {
        float sc = bng[tid] * rsqrtf(bnv[tid] + 1e-5f);
        sSc[tid] = sc;
        sSh[tid] = bnb[tid] - bnm[tid]*sc;
    } else if (tid < 96) {
        int o = tid - 64;
        sbias[o] = (o < OMC) ? ombias[o] : 0.f;
    }

    const int pl = tid & 127, jh = tid >> 7;
    const int pg = P0 + pl;
    const int py = pg / Wv, px = pg - py*Wv;

    // ldmatrix lane geometry
    const int laneA = lane & 15;
    const int rowA = wid*16 + laneA;                  // offc-phase A rows
    const int kbA  = (lane & 16) ? 1 : 0;
    const int rowB0 = (lane & 7) + ((lane & 16) ? 8 : 0);
    const int kbB   = (lane & 8) ? 1 : 0;

    // ================= Phase 1: offset/mask conv (M=128, N=32, 1-pass bf16) ===
    {
        const size_t chbase = (size_t)b*Cv*HWv + (size_t)(jh*32)*HWv;
        float acc[4][4];
        #pragma unroll
        for (int nt = 0; nt < 4; nt++)
            #pragma unroll
            for (int e = 0; e < 4; e++) acc[nt][e] = 0.f;

        for (int cc = 0; cc < NCH; cc++) {
            if (cc) __syncthreads();
            // stage B: 32 rows x 8 quads, hi only
            {
                int o = tid >> 3, cq = tid & 7;
                int gofs = o*CKK + cc*CKC + cq*8;
                *(uint4*)(smem + FS_BH + swz(o, cq)) = *(const uint4*)(omwh + gofs);
            }
            // build A (hi only): fixed tap cc
            {
                int yy = py + cc/3 - 1, xx = px + (cc % 3) - 1;
                bool val = ((unsigned)yy < (unsigned)Hv) && ((unsigned)xx < (unsigned)Wv);
                #pragma unroll
                for (int q = 0; q < 4; q++) {
                    uint32_t hq[4];
                    #pragma unroll
                    for (int wi = 0; wi < 4; wi++) {
                        int c0 = 8*q + 2*wi;
                        if (F32IN) {
                            const float* p = (const float*)omin + chbase + yy*Wv + xx;
                            float v0 = val ? __ldg(p + (size_t)c0*HWv) : 0.f;
                            float v1 = val ? __ldg(p + (size_t)(c0+1)*HWv) : 0.f;
                            hq[wi] = pack_bf16x2(v0, v1);
                        } else {
                            const __nv_bfloat16* p = (const __nv_bfloat16*)omin + chbase + yy*Wv + xx;
                            uint16_t v0 = val ? __bfloat16_as_ushort(__ldg(p + (size_t)c0*HWv)) : (uint16_t)0;
                            uint16_t v1 = val ? __bfloat16_as_ushort(__ldg(p + (size_t)(c0+1)*HWv)) : (uint16_t)0;
                            hq[wi] = (uint32_t)v0 | ((uint32_t)v1 << 16);
                        }
                    }
                    *(uint4*)(smem + FS_AH + swz(pl, jh*4 + q)) = make_uint4(hq[0],hq[1],hq[2],hq[3]);
                }
            }
            __syncthreads();
            // mma: 1 pass, N=32
            #pragma unroll
            for (int ks = 0; ks < 4; ks++) {
                uint32_t aAH = sbu + FS_AH + swz(rowA, ks*2 + kbA);
                uint32_t aH0,aH1,aH2,aH3;
                ldm_x4(aH0,aH1,aH2,aH3, aAH);
                uint32_t aB0 = sbu + FS_BH + swz(rowB0, ks*2 + kbB);
                uint32_t aB1 = sbu + FS_BH + swz(16 + rowB0, ks*2 + kbB);
                uint32_t bh0,bh1,bh2,bh3;
                ldm_x4(bh0,bh1,bh2,bh3, aB0);
                mma_bf16(acc[0], aH0,aH1,aH2,aH3, bh0,bh1);
                mma_bf16(acc[1], aH0,aH1,aH2,aH3, bh2,bh3);
                ldm_x4(bh0,bh1,bh2,bh3, aB1);
                mma_bf16(acc[2], aH0,aH1,aH2,aH3, bh0,bh1);
                mma_bf16(acc[3], aH0,aH1,aH2,aH3, bh2,bh3);
            }
        }

        __syncthreads();   // A/B tiles dead; om buffer safe to write
        #pragma unroll
        for (int nt = 0; nt < 4; nt++) {
            #pragma unroll
            for (int e = 0; e < 4; e++) {
                int o = nt*8 + 2*tq + (e & 1);
                if (o < OMC) {
                    int p = wid*16 + g + (e >> 1)*8;   // local px
                    sOm[p*OMST + o] = acc[nt][e] + sbias[o];
                }
            }
        }
    }
    __syncthreads();   // om ready

    // ================= Phase 2: gather tables from smem om =================
    for (int idx = tid; idx < KKv*MT; idx += TPB) {
        int k = idx >> 7, plt = idx & 127;
        int pxg2 = P0 + plt;
        int y = pxg2 / Wv, x = pxg2 - y*Wv;
        float dy = sOm[plt*OMST + 2*k];
        float dx = sOm[plt*OMST + 2*k+1];
        float mr = sOm[plt*OMST + 18+k];
        float m  = 1.f / (1.f + expf(-mr));
        float pyf = (float)y - 1.f + (float)(k/3) + dy;
        float pxf = (float)x - 1.f + (float)(k%3) + dx;
        float yf = floorf(pyf), xf = floorf(pxf);
        float ly = pyf - yf, lx = pxf - xf;
        int iy0 = (int)yf, ix0 = (int)xf;
        float vy0 = ((unsigned)iy0     < (unsigned)Hv) ? 1.f : 0.f;
        float vy1 = ((unsigned)(iy0+1) < (unsigned)Hv) ? 1.f : 0.f;
        float vx0 = ((unsigned)ix0     < (unsigned)Wv) ? 1.f : 0.f;
        float vx1 = ((unsigned)(ix0+1) < (unsigned)Wv) ? 1.f : 0.f;
        sWgt[idx] = make_float4((1.f-ly)*(1.f-lx)*m*vy0*vx0,
                                (1.f-ly)*lx      *m*vy0*vx1,
                                ly      *(1.f-lx)*m*vy1*vx0,
                                ly      *lx      *m*vy1*vx1);
        int iy0c = min(max(iy0,0),Hv-1), ix0c = min(max(ix0,0),Wv-1);
        int dy1 = (iy0 >= 0 && iy0 <= Hv-2) ? 1 : 0;
        int dx1 = (ix0 >= 0 && ix0 <= Wv-2) ? 1 : 0;
        sBase[idx] = iy0c | (ix0c<<8) | (dy1<<16) | (dx1<<17);
    }
    __syncthreads();

    // ================= Phase 3: DCN (M=128, N=64), warp tile 32px x 32o ======
    const float* srcB = src + (size_t)b*Cv*HWv + (size_t)jh*32*HWv;
    const int wq = wid & 3, wn = wid >> 2;   // px quarter, o half

    float acc[2][4][4];
    #pragma unroll
    for (int mt = 0; mt < 2; mt++)
        #pragma unroll
        for (int nt = 0; nt < 4; nt++)
            #pragma unroll
            for (int e = 0; e < 4; e++) acc[mt][nt][e] = 0.f;

    for (int cc = 0; cc < NCH; cc++) {
        if (cc) __syncthreads();

        // stage B chunk hi/lo: 64 rows x 8 quads (uint4)
        #pragma unroll
        for (int it = 0; it < 2; it++) {
            int idx = it*TPB + tid;
            int o = idx >> 3, cq = idx & 7;
            int gofs = o*CKK + cc*CKC + cq*8;
            uint32_t d = swz(o, cq);
            *(uint4*)(smem + FS_BH + d) = *(const uint4*)(wh + gofs);
            *(uint4*)(smem + FS_BL + d) = *(const uint4*)(wl + gofs);
        }

        // sample A chunk: fixed tap cc
        {
            int gi = cc*MT + pl;
            float4 cw = sWgt[gi];
            int ev = sBase[gi];
            int iy0 = ev & 255, ix0 = (ev>>8) & 255;
            int iy1 = iy0 + ((ev>>16)&1), ix1 = ix0 + ((ev>>17)&1);
            const float* pA = srcB + iy0*Wv + ix0;
            const float* pB = srcB + iy0*Wv + ix1;
            const float* pC = srcB + iy1*Wv + ix0;
            const float* pD = srcB + iy1*Wv + ix1;
            #pragma unroll
            for (int q = 0; q < 4; q++) {
                float vA[8], vB[8], vC[8], vD[8];
                #pragma unroll
                for (int ci = 0; ci < 8; ci++) {
                    size_t co = (size_t)(8*q + ci)*HWv;
                    vA[ci] = __ldg(pA + co);
                    vB[ci] = __ldg(pB + co);
                    vC[ci] = __ldg(pC + co);
                    vD[ci] = __ldg(pD + co);
                }
                uint32_t hq[4], lq[4];
                #pragma unroll
                for (int wi = 0; wi < 4; wi++) {
                    float s0 = cw.x*vA[2*wi]   + cw.y*vB[2*wi]
                             + cw.z*vC[2*wi]   + cw.w*vD[2*wi];
                    float s1 = cw.x*vA[2*wi+1] + cw.y*vB[2*wi+1]
                             + cw.z*vC[2*wi+1] + cw.w*vD[2*wi+1];
                    uint32_t p0 = split_pack(s0), p1 = split_pack(s1);
                    hq[wi] = __byte_perm(p0, p1, 0x5410);
                    lq[wi] = __byte_perm(p0, p1, 0x7632);
                }
                uint32_t d = swz(pl, jh*4 + q);
                *(uint4*)(smem + FS_AH + d) = make_uint4(hq[0],hq[1],hq[2],hq[3]);
                *(uint4*)(smem + FS_AL + d) = make_uint4(lq[0],lq[1],lq[2],lq[3]);
            }
        }
        __syncthreads();

        // MMA: 4 k-steps; warp covers 32 px (2 m-tiles) x 32 o (2 n-pairs)
        #pragma unroll
        for (int ks = 0; ks < 4; ks++) {
            uint32_t aH[2][4], aL[2][4];
            #pragma unroll
            for (int mt = 0; mt < 2; mt++) {
                uint32_t aAH = sbu + FS_AH + swz(wq*32 + mt*16 + laneA, ks*2 + kbA);
                ldm_x4(aH[mt][0],aH[mt][1],aH[mt][2],aH[mt][3], aAH);
                ldm_x4(aL[mt][0],aL[mt][1],aL[mt][2],aL[mt][3], aAH + (FS_AL - FS_AH));
            }
            #pragma unroll
            for (int np = 0; np < 2; np++) {
                uint32_t aB = sbu + FS_BH + swz(wn*32 + np*16 + rowB0, ks*2 + kbB);
                uint32_t bh0,bh1,bh2,bh3, bl0,bl1,bl2,bl3;
                ldm_x4(bh0,bh1,bh2,bh3, aB);
                ldm_x4(bl0,bl1,bl2,bl3, aB + (FS_BL - FS_BH));
                #pragma unroll
                for (int mt = 0; mt < 2; mt++) {
                    mma_bf16(acc[mt][2*np],   aH[mt][0],aH[mt][1],aH[mt][2],aH[mt][3], bh0,bh1);
                    mma_bf16(acc[mt][2*np],   aH[mt][0],aH[mt][1],aH[mt][2],aH[mt][3], bl0,bl1);
                    mma_bf16(acc[mt][2*np],   aL[mt][0],aL[mt][1],aL[mt][2],aL[mt][3], bh0,bh1);
                    mma_bf16(acc[mt][2*np+1], aH[mt][0],aH[mt][1],aH[mt][2],aH[mt][3], bh2,bh3);
                    mma_bf16(acc[mt][2*np+1], aH[mt][0],aH[mt][1],aH[mt][2],aH[mt][3], bl2,bl3);
                    mma_bf16(acc[mt][2*np+1], aL[mt][0],aL[mt][1],aL[mt][2],aL[mt][3], bh2,bh3);
                }
            }
        }
    }

    // epilogue: BN (+residual) + exact GELU (+ bf16 copy for layer 1)
    const size_t bofs = (size_t)b*Cv*HWv;
    #pragma unroll
    for (int mt = 0; mt < 2; mt++) {
        const int px0 = P0 + wq*32 + mt*16 + g;
        #pragma unroll
        for (int nt = 0; nt < 4; nt++) {
            #pragma unroll
            for (int e = 0; e < 4; e++) {
                int o  = wn*32 + nt*8 + 2*tq + (e & 1);
                int pxo = px0 + (e >> 1)*8;
                float v = acc[mt][nt][e] * sSc[o] + sSh[o];
                size_t ofs = bofs + (size_t)o*HWv + pxo;
                if (identity) v += __ldg(identity + ofs);
                v = gelu_exact(v);
                out[ofs] = v;
                if (midh) midh[ofs] = __float2bfloat16(v);
            }
        }
    }
}

// ---------------------------------------------------------------------------
extern "C" void kernel_launch(void* const* d_in, const int* in_sizes, int n_in,
                              void* d_out, int out_size)
{
    const float* x      = (const float*)d_in[0];
    const float* w_om1  = (const float*)d_in[1];
    const float* b_om1  = (const float*)d_in[2];
    const float* w_dcn1 = (const float*)d_in[3];
    const float* bn1g   = (const float*)d_in[4];
    const float* bn1b   = (const float*)d_in[5];
    const float* bn1m   = (const float*)d_in[6];
    const float* bn1v   = (const float*)d_in[7];
    const float* w_om2  = (const float*)d_in[8];
    const float* b_om2  = (const float*)d_in[9];
    const float* w_dcn2 = (const float*)d_in[10];
    const float* bn2g   = (const float*)d_in[11];
    const float* bn2b   = (const float*)d_in[12];
    const float* bn2m   = (const float*)d_in[13];
    const float* bn2v   = (const float*)d_in[14];
    float* out = (float*)d_out;

    float *mid;
    __nv_bfloat16 *midh, *wh1, *wl1, *wh2, *wl2, *omh1, *omh2;
    cudaGetSymbolAddress((void**)&mid,   g_mid);
    cudaGetSymbolAddress((void**)&midh,  g_midh);
    cudaGetSymbolAddress((void**)&wh1,   g_wh1);
    cudaGetSymbolAddress((void**)&wl1,   g_wl1);
    cudaGetSymbolAddress((void**)&wh2,   g_wh2);
    cudaGetSymbolAddress((void**)&wl2,   g_wl2);
    cudaGetSymbolAddress((void**)&omh1,  g_omh1);
    cudaGetSymbolAddress((void**)&omh2,  g_omh2);

    cudaFuncSetAttribute(fused_kernel<true>,  cudaFuncAttributeMaxDynamicSharedMemorySize, FS_TOT);
    cudaFuncSetAttribute(fused_kernel<false>, cudaFuncAttributeMaxDynamicSharedMemorySize, FS_TOT);

    prep_kernel<<<(Cv*CKK + 255)/256, 256>>>(w_dcn1, w_dcn2, w_om1, w_om2);

    dim3 grid(HWv/MT, Bv);   // 200 x 4

    fused_kernel<true><<<grid, TPB, FS_TOT>>>(x, omh1, b_om1,
        x, wh1, wl1, bn1g, bn1b, bn1m, bn1v, nullptr, mid, midh);

    fused_kernel<false><<<grid, TPB, FS_TOT>>>(midh, omh2, b_om2,
        mid, wh2, wl2, bn2g, bn2b, bn2m, bn2v, x, out, nullptr);
}